// round 1
// baseline (speedup 1.0000x reference)
#include <cuda_runtime.h>
#include <math.h>

#define D_MODEL 1024
#define NHEADS  16
#define DHEAD   64
#define BATCH   2
#define SEQ     2048
#define MROWS   (BATCH*SEQ)          // 4096
#define BHTOT   (BATCH*NHEADS)       // 32

// ---------------- scratch (no allocations allowed) ----------------
__device__ float g_Q[(size_t)BHTOT*SEQ*DHEAD];   // [B,H,S,Dh] 16MB
__device__ float g_K[(size_t)BHTOT*SEQ*DHEAD];
__device__ float g_V[(size_t)BHTOT*SEQ*DHEAD];
__device__ float g_O[(size_t)MROWS*D_MODEL];     // [B,S,D]    16MB

// =====================================================================
// GEMM:  C = A[M,K] @ W[N,K]^T + bias[N]
// BM=BN=128, BK=16, 256 threads, 8x8 microtile per thread.
// OUT_BHSD=true scatters output into [B,H,S,Dh] (for Q/K/V).
// =====================================================================
template<bool OUT_BHSD>
__global__ __launch_bounds__(256)
void gemm_nt(const float* __restrict__ A, const float* __restrict__ W,
             const float* __restrict__ bias, float* __restrict__ C)
{
    constexpr int K  = D_MODEL;
    constexpr int LD = 132;               // 128 + 4 pad, keeps float4 smem reads 16B aligned
    __shared__ float As[16][LD];
    __shared__ float Bs[16][LD];

    const int tid = threadIdx.x;
    const int m0  = blockIdx.y * 128;
    const int n0  = blockIdx.x * 128;
    const int ty  = tid >> 4;             // 0..15
    const int tx  = tid & 15;             // 0..15

    const int frow = tid >> 2;            // 0..63
    const int fk   = (tid & 3) << 2;      // 0,4,8,12

    float acc[8][8];
    #pragma unroll
    for (int i = 0; i < 8; i++)
        #pragma unroll
        for (int j = 0; j < 8; j++) acc[i][j] = 0.f;

    const float* Ap0 = A + (size_t)(m0 + frow) * K + fk;
    const float* Ap1 = Ap0 + (size_t)64 * K;
    const float* Wp0 = W + (size_t)(n0 + frow) * K + fk;
    const float* Wp1 = Wp0 + (size_t)64 * K;

    for (int k0 = 0; k0 < K; k0 += 16) {
        float4 a0 = *(const float4*)(Ap0 + k0);
        float4 a1 = *(const float4*)(Ap1 + k0);
        float4 b0 = *(const float4*)(Wp0 + k0);
        float4 b1 = *(const float4*)(Wp1 + k0);
        __syncthreads();
        As[fk+0][frow]    = a0.x; As[fk+1][frow]    = a0.y;
        As[fk+2][frow]    = a0.z; As[fk+3][frow]    = a0.w;
        As[fk+0][frow+64] = a1.x; As[fk+1][frow+64] = a1.y;
        As[fk+2][frow+64] = a1.z; As[fk+3][frow+64] = a1.w;
        Bs[fk+0][frow]    = b0.x; Bs[fk+1][frow]    = b0.y;
        Bs[fk+2][frow]    = b0.z; Bs[fk+3][frow]    = b0.w;
        Bs[fk+0][frow+64] = b1.x; Bs[fk+1][frow+64] = b1.y;
        Bs[fk+2][frow+64] = b1.z; Bs[fk+3][frow+64] = b1.w;
        __syncthreads();

        #pragma unroll
        for (int kk = 0; kk < 16; kk++) {
            float4 A0 = *(const float4*)&As[kk][ty*8];
            float4 A1 = *(const float4*)&As[kk][ty*8+4];
            float4 B0 = *(const float4*)&Bs[kk][tx*8];
            float4 B1 = *(const float4*)&Bs[kk][tx*8+4];
            float av[8] = {A0.x,A0.y,A0.z,A0.w,A1.x,A1.y,A1.z,A1.w};
            float bv[8] = {B0.x,B0.y,B0.z,B0.w,B1.x,B1.y,B1.z,B1.w};
            #pragma unroll
            for (int ii = 0; ii < 8; ii++)
                #pragma unroll
                for (int jj = 0; jj < 8; jj++)
                    acc[ii][jj] += av[ii] * bv[jj];
        }
    }

    #pragma unroll
    for (int ii = 0; ii < 8; ii++) {
        const int m = m0 + ty*8 + ii;
        #pragma unroll
        for (int j4 = 0; j4 < 2; j4++) {
            const int n = n0 + tx*8 + j4*4;
            float4 v;
            v.x = acc[ii][j4*4+0] + bias[n+0];
            v.y = acc[ii][j4*4+1] + bias[n+1];
            v.z = acc[ii][j4*4+2] + bias[n+2];
            v.w = acc[ii][j4*4+3] + bias[n+3];
            if (OUT_BHSD) {
                const int b = m >> 11;        // /SEQ
                const int s = m & (SEQ-1);
                const int h = n >> 6;
                const int d = n & 63;
                *(float4*)(C + (((size_t)(b*NHEADS + h)*SEQ + s) << 6) + d) = v;
            } else {
                *(float4*)(C + (size_t)m * D_MODEL + n) = v;
            }
        }
    }
}

// =====================================================================
// RoPE (rotate-half, base 10000) applied in-place to Q and K [B,H,S,Dh]
// =====================================================================
__global__ void rope_kernel(float* __restrict__ Q, float* __restrict__ Kt)
{
    const unsigned t = blockIdx.x * blockDim.x + threadIdx.x;  // < 2^21
    float* P = blockIdx.y ? Kt : Q;
    const int d  = t & 31;
    const int s  = (t >> 5) & (SEQ - 1);
    const int bh = t >> 16;
    const size_t base = ((size_t)bh * SEQ + s) * DHEAD;

    // inv_freq = 10000^(-d/32) = 2^(-d * log2(10000)/32)
    const float inv = exp2f(-(float)d * 0.41524101186091903f);
    const float ang = (float)s * inv;
    float sn, cs;
    sincosf(ang, &sn, &cs);

    const float x1 = P[base + d];
    const float x2 = P[base + d + 32];
    P[base + d]      = x1 * cs - x2 * sn;
    P[base + d + 32] = x2 * cs + x1 * sn;
}

// =====================================================================
// Flash attention (fp32, causal). One CTA = (b,h, 64-row q-block).
// BQ=BKV=64, 256 threads, 4x4 microtile. Writes O in [B,S,D] layout.
// =====================================================================
#define ATTN_LD   68
#define ATTN_SMEM (4 * 64 * ATTN_LD * 4)

__global__ __launch_bounds__(256)
void attn_kernel(const float* __restrict__ Q, const float* __restrict__ Kg,
                 const float* __restrict__ Vg, float* __restrict__ O)
{
    extern __shared__ float sm[];
    const int LD = ATTN_LD;
    float* Qs = sm;
    float* Ks = Qs + 64*LD;
    float* Vs = Ks + 64*LD;
    float* Ps = Vs + 64*LD;

    const int qb  = gridDim.x - 1 - blockIdx.x;   // big blocks first
    const int bh  = blockIdx.y;
    const int tid = threadIdx.x;
    const int ty  = tid >> 4;
    const int tx  = tid & 15;
    const int qs  = qb * 64;

    const float* Qb = Q  + (size_t)bh * SEQ * DHEAD;
    const float* Kb = Kg + (size_t)bh * SEQ * DHEAD;
    const float* Vb = Vg + (size_t)bh * SEQ * DHEAD;

    const int lrow = tid >> 4;          // 0..15
    const int lc   = (tid & 15) << 2;   // float col (x4)

    #pragma unroll
    for (int p = 0; p < 4; p++) {
        const int r = lrow + p*16;
        *(float4*)&Qs[r*LD + lc] = *(const float4*)(Qb + (size_t)(qs + r)*DHEAD + lc);
    }

    float m_i[4], l_i[4], acc[4][4];
    #pragma unroll
    for (int ii = 0; ii < 4; ii++) {
        m_i[ii] = -INFINITY; l_i[ii] = 0.f;
        #pragma unroll
        for (int jj = 0; jj < 4; jj++) acc[ii][jj] = 0.f;
    }

    for (int t = 0; t <= qb; t++) {
        const int ks = t * 64;
        __syncthreads();
        #pragma unroll
        for (int p = 0; p < 4; p++) {
            const int r = lrow + p*16;
            *(float4*)&Ks[r*LD + lc] = *(const float4*)(Kb + (size_t)(ks + r)*DHEAD + lc);
            *(float4*)&Vs[r*LD + lc] = *(const float4*)(Vb + (size_t)(ks + r)*DHEAD + lc);
        }
        __syncthreads();

        float sc[4][4];
        #pragma unroll
        for (int ii = 0; ii < 4; ii++)
            #pragma unroll
            for (int jj = 0; jj < 4; jj++) sc[ii][jj] = 0.f;

        #pragma unroll 4
        for (int d4 = 0; d4 < 16; d4++) {
            float4 qv[4], kv[4];
            #pragma unroll
            for (int ii = 0; ii < 4; ii++)
                qv[ii] = *(const float4*)&Qs[(ty*4+ii)*LD + d4*4];
            #pragma unroll
            for (int jj = 0; jj < 4; jj++)
                kv[jj] = *(const float4*)&Ks[(tx*4+jj)*LD + d4*4];
            #pragma unroll
            for (int ii = 0; ii < 4; ii++)
                #pragma unroll
                for (int jj = 0; jj < 4; jj++)
                    sc[ii][jj] += qv[ii].x*kv[jj].x + qv[ii].y*kv[jj].y
                                + qv[ii].z*kv[jj].z + qv[ii].w*kv[jj].w;
        }

        const float scale = 0.125f;   // 1/sqrt(64)
        if (t == qb) {
            #pragma unroll
            for (int ii = 0; ii < 4; ii++)
                #pragma unroll
                for (int jj = 0; jj < 4; jj++)
                    sc[ii][jj] = (tx*4+jj <= ty*4+ii) ? sc[ii][jj]*scale : -INFINITY;
        } else {
            #pragma unroll
            for (int ii = 0; ii < 4; ii++)
                #pragma unroll
                for (int jj = 0; jj < 4; jj++) sc[ii][jj] *= scale;
        }

        #pragma unroll
        for (int ii = 0; ii < 4; ii++) {
            float rm = fmaxf(fmaxf(sc[ii][0], sc[ii][1]), fmaxf(sc[ii][2], sc[ii][3]));
            #pragma unroll
            for (int o = 8; o > 0; o >>= 1)
                rm = fmaxf(rm, __shfl_xor_sync(0xffffffffu, rm, o));
            const float mn    = fmaxf(m_i[ii], rm);
            const float alpha = __expf(m_i[ii] - mn);
            m_i[ii] = mn;
            float rs = 0.f;
            #pragma unroll
            for (int jj = 0; jj < 4; jj++) {
                const float p = __expf(sc[ii][jj] - mn);
                sc[ii][jj] = p;
                rs += p;
            }
            #pragma unroll
            for (int o = 8; o > 0; o >>= 1)
                rs += __shfl_xor_sync(0xffffffffu, rs, o);
            l_i[ii] = l_i[ii]*alpha + rs;
            #pragma unroll
            for (int jj = 0; jj < 4; jj++) acc[ii][jj] *= alpha;
            *(float4*)&Ps[(ty*4+ii)*LD + tx*4] =
                make_float4(sc[ii][0], sc[ii][1], sc[ii][2], sc[ii][3]);
        }
        __syncthreads();

        #pragma unroll 4
        for (int j4 = 0; j4 < 16; j4++) {
            float4 pv[4];
            #pragma unroll
            for (int ii = 0; ii < 4; ii++)
                pv[ii] = *(const float4*)&Ps[(ty*4+ii)*LD + j4*4];
            const float4 v0 = *(const float4*)&Vs[(j4*4+0)*LD + tx*4];
            const float4 v1 = *(const float4*)&Vs[(j4*4+1)*LD + tx*4];
            const float4 v2 = *(const float4*)&Vs[(j4*4+2)*LD + tx*4];
            const float4 v3 = *(const float4*)&Vs[(j4*4+3)*LD + tx*4];
            #pragma unroll
            for (int ii = 0; ii < 4; ii++) {
                acc[ii][0] += pv[ii].x*v0.x + pv[ii].y*v1.x + pv[ii].z*v2.x + pv[ii].w*v3.x;
                acc[ii][1] += pv[ii].x*v0.y + pv[ii].y*v1.y + pv[ii].z*v2.y + pv[ii].w*v3.y;
                acc[ii][2] += pv[ii].x*v0.z + pv[ii].y*v1.z + pv[ii].z*v2.z + pv[ii].w*v3.z;
                acc[ii][3] += pv[ii].x*v0.w + pv[ii].y*v1.w + pv[ii].z*v2.w + pv[ii].w*v3.w;
            }
        }
    }

    const int b = bh >> 4;
    const int h = bh & 15;
    #pragma unroll
    for (int ii = 0; ii < 4; ii++) {
        const float inv  = 1.f / l_i[ii];
        const int   srow = qs + ty*4 + ii;
        float4 o4 = make_float4(acc[ii][0]*inv, acc[ii][1]*inv,
                                acc[ii][2]*inv, acc[ii][3]*inv);
        *(float4*)(O + (size_t)(b*SEQ + srow)*D_MODEL + h*DHEAD + tx*4) = o4;
    }
}

// =====================================================================
// launch
// =====================================================================
extern "C" void kernel_launch(void* const* d_in, const int* in_sizes, int n_in,
                              void* d_out, int out_size)
{
    (void)in_sizes; (void)n_in; (void)out_size;
    const float* x  = (const float*)d_in[0];
    const float* Wq = (const float*)d_in[1];
    const float* bq = (const float*)d_in[2];
    const float* Wk = (const float*)d_in[3];
    const float* bk = (const float*)d_in[4];
    const float* Wv = (const float*)d_in[5];
    const float* bv = (const float*)d_in[6];
    const float* Wo = (const float*)d_in[7];
    const float* bo = (const float*)d_in[8];
    float* out = (float*)d_out;

    float *Qp, *Kp, *Vp, *Op;
    cudaGetSymbolAddress((void**)&Qp, g_Q);
    cudaGetSymbolAddress((void**)&Kp, g_K);
    cudaGetSymbolAddress((void**)&Vp, g_V);
    cudaGetSymbolAddress((void**)&Op, g_O);

    const dim3 gg(D_MODEL/128, MROWS/128);   // (8, 32)
    gemm_nt<true><<<gg, 256>>>(x, Wq, bq, Qp);
    gemm_nt<true><<<gg, 256>>>(x, Wk, bk, Kp);
    gemm_nt<true><<<gg, 256>>>(x, Wv, bv, Vp);

    const int rthreads = BHTOT * SEQ * 32;   // 2^21 pairs per tensor
    rope_kernel<<<dim3(rthreads/256, 2), 256>>>(Qp, Kp);

    cudaFuncSetAttribute(attn_kernel,
                         cudaFuncAttributeMaxDynamicSharedMemorySize, ATTN_SMEM);
    attn_kernel<<<dim3(SEQ/64, BHTOT), 256, ATTN_SMEM>>>(Qp, Kp, Vp, Op);

    gemm_nt<false><<<gg, 256>>>(Op, Wo, bo, out);
}

// round 3
// speedup vs baseline: 2.6709x; 2.6709x over previous
#include <cuda_runtime.h>
#include <cuda_bf16.h>
#include <math.h>
#include <stdint.h>

#define D_MODEL 1024
#define NHEADS  16
#define DHEAD   64
#define BATCH   2
#define SEQ     2048
#define MROWS   (BATCH*SEQ)          // 4096
#define BHTOT   (BATCH*NHEADS)       // 32

// ---------------- scratch (no allocations allowed) ----------------
__device__ float g_Q[(size_t)BHTOT*SEQ*DHEAD];   // [B,H,S,Dh]
__device__ float g_K[(size_t)BHTOT*SEQ*DHEAD];
__device__ float g_V[(size_t)BHTOT*SEQ*DHEAD];
__device__ float g_O[(size_t)MROWS*D_MODEL];     // [B,S,D]

// =====================================================================
// helpers: sm_80-class tensor core path (works on plain sm_103 target)
// =====================================================================
__device__ __forceinline__ uint32_t smem_u32(const void* p) {
    uint32_t a;
    asm("{ .reg .u64 t; cvta.to.shared.u64 t, %1; cvt.u32.u64 %0, t; }"
        : "=r"(a) : "l"(p));
    return a;
}
__device__ __forceinline__ void ldsm4(uint32_t r[4], uint32_t a) {
    asm volatile("ldmatrix.sync.aligned.m8n8.x4.shared.b16 {%0,%1,%2,%3}, [%4];"
                 : "=r"(r[0]), "=r"(r[1]), "=r"(r[2]), "=r"(r[3]) : "r"(a));
}
__device__ __forceinline__ void ldsm4t(uint32_t r[4], uint32_t a) {
    asm volatile("ldmatrix.sync.aligned.m8n8.x4.trans.shared.b16 {%0,%1,%2,%3}, [%4];"
                 : "=r"(r[0]), "=r"(r[1]), "=r"(r[2]), "=r"(r[3]) : "r"(a));
}
__device__ __forceinline__ void mma_bf16(float d[4], const uint32_t a[4],
                                         uint32_t b0, uint32_t b1) {
    asm volatile(
        "mma.sync.aligned.m16n8k16.row.col.f32.bf16.bf16.f32 "
        "{%0,%1,%2,%3}, {%4,%5,%6,%7}, {%8,%9}, {%0,%1,%2,%3};"
        : "+f"(d[0]), "+f"(d[1]), "+f"(d[2]), "+f"(d[3])
        : "r"(a[0]), "r"(a[1]), "r"(a[2]), "r"(a[3]), "r"(b0), "r"(b1));
}
// split fp32 pair -> packed bf16x2 hi and residual lo (Ootomo bf16x3 scheme)
__device__ __forceinline__ void split2(float v0, float v1, uint32_t& hi, uint32_t& lo) {
    __nv_bfloat16 h0 = __float2bfloat16(v0);
    __nv_bfloat16 h1 = __float2bfloat16(v1);
    __nv_bfloat162 H = __halves2bfloat162(h0, h1);
    hi = *reinterpret_cast<uint32_t*>(&H);
    __nv_bfloat162 L = __floats2bfloat162_rn(v0 - __bfloat162float(h0),
                                             v1 - __bfloat162float(h1));
    lo = *reinterpret_cast<uint32_t*>(&L);
}

// =====================================================================
// GEMM (bf16x3 mma.sync): C[M,N] = A[M,K] @ W[N,K]^T + bias[N]
// BM=BN=128, BK=32, 256 thr, 8 warps as 4(m)x2(n), warp tile 32x64.
// smem rows padded to 40 bf16 (80B) -> conflict-free ldmatrix.
// =====================================================================
#define GBK    32
#define GSTB   80                      // smem row stride bytes (40 bf16)
#define GA_SZ  (128*GSTB)              // 10240 per (hi or lo) tile
#define GSTAGE (4*GA_SZ)               // Ah, Al, Bh, Bl
#define GEMM_SMEM (2*GSTAGE)           // 81920

template<bool OUT_BHSD>
__global__ __launch_bounds__(256)
void gemm_bf16x3(const float* __restrict__ A, const float* __restrict__ W,
                 const float* __restrict__ bias, float* __restrict__ C)
{
    extern __shared__ char sm[];
    const uint32_t sbase = smem_u32(sm);
    const int tid  = threadIdx.x;
    const int wid  = tid >> 5, lane = tid & 31;
    const int wm   = wid & 3,  wn   = wid >> 2;
    const int m0   = blockIdx.y * 128, n0 = blockIdx.x * 128;

    float acc[2][8][4] = {};

    const int lrow = tid >> 1;             // 0..127
    const int lcb  = (tid & 1) * 16;       // 0 / 16
    const float* Ag = A + (size_t)(m0 + lrow) * 1024 + lcb;
    const float* Wg = W + (size_t)(n0 + lrow) * 1024 + lcb;

    float av[16], wv[16];
    // prologue load (stage 0)
    #pragma unroll
    for (int j = 0; j < 4; j++) {
        *(float4*)&av[j*4] = *(const float4*)(Ag + j*4);
        *(float4*)&wv[j*4] = *(const float4*)(Wg + j*4);
    }
    // store stage 0
    {
        char* base = sm;
        uint32_t h[8], l[8];
        const uint32_t off = lrow*GSTB + lcb*2;
        #pragma unroll
        for (int i = 0; i < 8; i++) split2(av[2*i], av[2*i+1], h[i], l[i]);
        *(uint4*)(base + off)              = make_uint4(h[0],h[1],h[2],h[3]);
        *(uint4*)(base + off + 16)         = make_uint4(h[4],h[5],h[6],h[7]);
        *(uint4*)(base + GA_SZ + off)      = make_uint4(l[0],l[1],l[2],l[3]);
        *(uint4*)(base + GA_SZ + off + 16) = make_uint4(l[4],l[5],l[6],l[7]);
        #pragma unroll
        for (int i = 0; i < 8; i++) split2(wv[2*i], wv[2*i+1], h[i], l[i]);
        *(uint4*)(base + 2*GA_SZ + off)      = make_uint4(h[0],h[1],h[2],h[3]);
        *(uint4*)(base + 2*GA_SZ + off + 16) = make_uint4(h[4],h[5],h[6],h[7]);
        *(uint4*)(base + 3*GA_SZ + off)      = make_uint4(l[0],l[1],l[2],l[3]);
        *(uint4*)(base + 3*GA_SZ + off + 16) = make_uint4(l[4],l[5],l[6],l[7]);
    }
    __syncthreads();

    for (int s = 0; s < 32; s++) {
        const int buf = s & 1;
        if (s < 31) {
            const int k1 = (s + 1) * GBK;
            #pragma unroll
            for (int j = 0; j < 4; j++) {
                *(float4*)&av[j*4] = *(const float4*)(Ag + k1 + j*4);
                *(float4*)&wv[j*4] = *(const float4*)(Wg + k1 + j*4);
            }
        }
        // compute from smem[buf]
        const uint32_t sA = sbase + buf * GSTAGE;
        const uint32_t sB = sA + 2*GA_SZ;
        const uint32_t lrq = (lane & 15);
        const uint32_t lch = ((lane >> 4) << 3) * 2;   // byte offset of col half
        #pragma unroll
        for (int kk = 0; kk < 2; kk++) {
            uint32_t ah[2][4], al[2][4];
            #pragma unroll
            for (int mi = 0; mi < 2; mi++) {
                uint32_t addr = sA + (wm*32 + mi*16 + lrq)*GSTB + kk*32 + lch;
                ldsm4(ah[mi], addr);
                ldsm4(al[mi], addr + GA_SZ);
            }
            #pragma unroll
            for (int g = 0; g < 4; g++) {
                uint32_t bh[4], bl[4];
                uint32_t baddr = sB + (wn*64 + g*16 + lrq)*GSTB + kk*32 + lch;
                ldsm4(bh, baddr);
                ldsm4(bl, baddr + GA_SZ);
                #pragma unroll
                for (int mi = 0; mi < 2; mi++) {
                    mma_bf16(acc[mi][2*g],   ah[mi], bh[0], bh[2]);
                    mma_bf16(acc[mi][2*g+1], ah[mi], bh[1], bh[3]);
                    mma_bf16(acc[mi][2*g],   ah[mi], bl[0], bl[2]);
                    mma_bf16(acc[mi][2*g+1], ah[mi], bl[1], bl[3]);
                    mma_bf16(acc[mi][2*g],   al[mi], bh[0], bh[2]);
                    mma_bf16(acc[mi][2*g+1], al[mi], bh[1], bh[3]);
                }
            }
        }
        if (s < 31) {
            char* base = sm + (buf ^ 1) * GSTAGE;
            uint32_t h[8], l[8];
            const uint32_t off = lrow*GSTB + lcb*2;
            #pragma unroll
            for (int i = 0; i < 8; i++) split2(av[2*i], av[2*i+1], h[i], l[i]);
            *(uint4*)(base + off)              = make_uint4(h[0],h[1],h[2],h[3]);
            *(uint4*)(base + off + 16)         = make_uint4(h[4],h[5],h[6],h[7]);
            *(uint4*)(base + GA_SZ + off)      = make_uint4(l[0],l[1],l[2],l[3]);
            *(uint4*)(base + GA_SZ + off + 16) = make_uint4(l[4],l[5],l[6],l[7]);
            #pragma unroll
            for (int i = 0; i < 8; i++) split2(wv[2*i], wv[2*i+1], h[i], l[i]);
            *(uint4*)(base + 2*GA_SZ + off)      = make_uint4(h[0],h[1],h[2],h[3]);
            *(uint4*)(base + 2*GA_SZ + off + 16) = make_uint4(h[4],h[5],h[6],h[7]);
            *(uint4*)(base + 3*GA_SZ + off)      = make_uint4(l[0],l[1],l[2],l[3]);
            *(uint4*)(base + 3*GA_SZ + off + 16) = make_uint4(l[4],l[5],l[6],l[7]);
        }
        __syncthreads();
    }

    // epilogue
    const int rbase = m0 + wm*32 + (lane >> 2);
    const int cbase = n0 + wn*64 + (lane & 3)*2;
    #pragma unroll
    for (int mi = 0; mi < 2; mi++) {
        #pragma unroll
        for (int j = 0; j < 8; j++) {
            const int c = cbase + j*8;
            const float2 b2 = *(const float2*)(bias + c);
            const int r0 = rbase + mi*16, r1 = r0 + 8;
            float2 v0 = make_float2(acc[mi][j][0] + b2.x, acc[mi][j][1] + b2.y);
            float2 v1 = make_float2(acc[mi][j][2] + b2.x, acc[mi][j][3] + b2.y);
            if (OUT_BHSD) {
                const int h = c >> 6, d = c & 63;
                const int b0b = r0 >> 11, s0 = r0 & (SEQ-1);
                const int b1b = r1 >> 11, s1 = r1 & (SEQ-1);
                *(float2*)(C + (((size_t)(b0b*NHEADS + h)*SEQ + s0) << 6) + d) = v0;
                *(float2*)(C + (((size_t)(b1b*NHEADS + h)*SEQ + s1) << 6) + d) = v1;
            } else {
                *(float2*)(C + (size_t)r0 * D_MODEL + c) = v0;
                *(float2*)(C + (size_t)r1 * D_MODEL + c) = v1;
            }
        }
    }
}

// =====================================================================
// RoPE (rotate-half, base 10000) in-place on Q and K [B,H,S,Dh]
// =====================================================================
__global__ void rope_kernel(float* __restrict__ Q, float* __restrict__ Kt)
{
    const unsigned t = blockIdx.x * blockDim.x + threadIdx.x;
    float* P = blockIdx.y ? Kt : Q;
    const int d  = t & 31;
    const int s  = (t >> 5) & (SEQ - 1);
    const int bh = t >> 16;
    const size_t base = ((size_t)bh * SEQ + s) * DHEAD;

    const float inv = exp2f(-(float)d * 0.41524101186091903f);
    const float ang = (float)s * inv;
    float sn, cs;
    sincosf(ang, &sn, &cs);

    const float x1 = P[base + d];
    const float x2 = P[base + d + 32];
    P[base + d]      = x1 * cs - x2 * sn;
    P[base + d + 32] = x2 * cs + x1 * sn;
}

// =====================================================================
// Flash attention, bf16x3 mma.sync. CTA = (bh, 128-q-rows); 8 warps,
// warp w owns q rows [w*16, w*16+16). BKV=64. P kept in registers.
// smem rows padded to 72 bf16 (144B) -> conflict-free ldmatrix.
// =====================================================================
#define ASTRB  144
#define AQ_SZ  (128*ASTRB)     // 18432 per (hi|lo)
#define AK_SZ  (64*ASTRB)      // 9216  per (hi|lo)
#define ATTN_SMEM (2*AQ_SZ + 4*AK_SZ)   // 73728

__global__ __launch_bounds__(256)
void attn_mma(const float* __restrict__ Q, const float* __restrict__ Kg,
              const float* __restrict__ Vg, float* __restrict__ O)
{
    extern __shared__ char sm[];
    const uint32_t sbase = smem_u32(sm);
    const int tid = threadIdx.x, wid = tid >> 5, lane = tid & 31;
    const int qb  = gridDim.x - 1 - blockIdx.x;    // big blocks first
    const int bh  = blockIdx.y;
    const int qs  = qb * 128;

    const float* Qb = Q  + (size_t)bh * SEQ * DHEAD;
    const float* Kb = Kg + (size_t)bh * SEQ * DHEAD;
    const float* Vb = Vg + (size_t)bh * SEQ * DHEAD;

    const uint32_t sQh = sbase;
    const uint32_t sKh = sbase + 2*AQ_SZ;
    const uint32_t sVh = sKh + 2*AK_SZ;

    // ---- load & split Q (row = tid/2, 32 cols each) ----
    {
        const int row = tid >> 1, cb = (tid & 1) * 32;
        float q[32];
        #pragma unroll
        for (int j = 0; j < 8; j++)
            *(float4*)&q[j*4] = *(const float4*)(Qb + (size_t)(qs + row)*DHEAD + cb + j*4);
        uint32_t h[16], l[16];
        #pragma unroll
        for (int i = 0; i < 16; i++) split2(q[2*i], q[2*i+1], h[i], l[i]);
        char* dst = sm + row*ASTRB + cb*2;
        #pragma unroll
        for (int j = 0; j < 4; j++) {
            *(uint4*)(dst + j*16)         = make_uint4(h[4*j],h[4*j+1],h[4*j+2],h[4*j+3]);
            *(uint4*)(dst + AQ_SZ + j*16) = make_uint4(l[4*j],l[4*j+1],l[4*j+2],l[4*j+3]);
        }
    }

    float o[8][4] = {};
    float m0r = -1e30f, m1r = -1e30f, l0r = 0.f, l1r = 0.f;

    const int   nt   = 2*(qb + 1);
    const int   krow = tid >> 2, kcb = (tid & 3) * 16;   // K/V loader map
    const uint32_t lrq = (lane & 15);
    const uint32_t lch = ((lane >> 4) << 3) * 2;

    for (int t = 0; t < nt; t++) {
        const int ks = t * 64;
        // prefetch K/V tile into regs
        float kv[16], vv[16];
        #pragma unroll
        for (int j = 0; j < 4; j++) {
            *(float4*)&kv[j*4] = *(const float4*)(Kb + (size_t)(ks + krow)*DHEAD + kcb + j*4);
            *(float4*)&vv[j*4] = *(const float4*)(Vb + (size_t)(ks + krow)*DHEAD + kcb + j*4);
        }
        __syncthreads();   // prior tile's reads done
        {
            uint32_t h[8], l[8];
            char* kd = sm + 2*AQ_SZ + krow*ASTRB + kcb*2;
            #pragma unroll
            for (int i = 0; i < 8; i++) split2(kv[2*i], kv[2*i+1], h[i], l[i]);
            *(uint4*)(kd)              = make_uint4(h[0],h[1],h[2],h[3]);
            *(uint4*)(kd + 16)         = make_uint4(h[4],h[5],h[6],h[7]);
            *(uint4*)(kd + AK_SZ)      = make_uint4(l[0],l[1],l[2],l[3]);
            *(uint4*)(kd + AK_SZ + 16) = make_uint4(l[4],l[5],l[6],l[7]);
            char* vd = kd + 2*AK_SZ;
            #pragma unroll
            for (int i = 0; i < 8; i++) split2(vv[2*i], vv[2*i+1], h[i], l[i]);
            *(uint4*)(vd)              = make_uint4(h[0],h[1],h[2],h[3]);
            *(uint4*)(vd + 16)         = make_uint4(h[4],h[5],h[6],h[7]);
            *(uint4*)(vd + AK_SZ)      = make_uint4(l[0],l[1],l[2],l[3]);
            *(uint4*)(vd + AK_SZ + 16) = make_uint4(l[4],l[5],l[6],l[7]);
        }
        __syncthreads();

        // warps whose rows are all above-mask skip compute entirely
        if (qs + wid*16 + 15 < ks) continue;

        // ---- S = Q K^T ----
        float s[8][4] = {};
        #pragma unroll
        for (int kk = 0; kk < 4; kk++) {
            uint32_t qh[4], ql[4];
            const uint32_t qaddr = sQh + (wid*16 + lrq)*ASTRB + kk*32 + lch;
            ldsm4(qh, qaddr);
            ldsm4(ql, qaddr + AQ_SZ);
            #pragma unroll
            for (int g = 0; g < 4; g++) {
                uint32_t khf[4], klf[4];
                const uint32_t kaddr = sKh + (g*16 + lrq)*ASTRB + kk*32 + lch;
                ldsm4(khf, kaddr);
                ldsm4(klf, kaddr + AK_SZ);
                mma_bf16(s[2*g],   qh, khf[0], khf[2]);
                mma_bf16(s[2*g+1], qh, khf[1], khf[3]);
                mma_bf16(s[2*g],   qh, klf[0], klf[2]);
                mma_bf16(s[2*g+1], qh, klf[1], klf[3]);
                mma_bf16(s[2*g],   ql, khf[0], khf[2]);
                mma_bf16(s[2*g+1], ql, khf[1], khf[3]);
            }
        }

        // ---- scale + causal mask ----
        const int r0 = qs + wid*16 + (lane >> 2);
        const int r1 = r0 + 8;
        const float SC = 0.125f;
        if (ks + 63 > qs + wid*16) {   // tile may touch diagonal for this warp
            #pragma unroll
            for (int j = 0; j < 8; j++) {
                const int c = ks + j*8 + (lane & 3)*2;
                s[j][0] = (c     <= r0) ? s[j][0]*SC : -1e30f;
                s[j][1] = (c + 1 <= r0) ? s[j][1]*SC : -1e30f;
                s[j][2] = (c     <= r1) ? s[j][2]*SC : -1e30f;
                s[j][3] = (c + 1 <= r1) ? s[j][3]*SC : -1e30f;
            }
        } else {
            #pragma unroll
            for (int j = 0; j < 8; j++) {
                s[j][0] *= SC; s[j][1] *= SC; s[j][2] *= SC; s[j][3] *= SC;
            }
        }

        // ---- online softmax (rows r0, r1 per thread, reduced in quads) ----
        float mx0 = -1e30f, mx1 = -1e30f;
        #pragma unroll
        for (int j = 0; j < 8; j++) {
            mx0 = fmaxf(mx0, fmaxf(s[j][0], s[j][1]));
            mx1 = fmaxf(mx1, fmaxf(s[j][2], s[j][3]));
        }
        mx0 = fmaxf(mx0, __shfl_xor_sync(0xffffffffu, mx0, 1));
        mx0 = fmaxf(mx0, __shfl_xor_sync(0xffffffffu, mx0, 2));
        mx1 = fmaxf(mx1, __shfl_xor_sync(0xffffffffu, mx1, 1));
        mx1 = fmaxf(mx1, __shfl_xor_sync(0xffffffffu, mx1, 2));
        const float mn0 = fmaxf(m0r, mx0), mn1 = fmaxf(m1r, mx1);
        const float a0 = __expf(m0r - mn0), a1 = __expf(m1r - mn1);
        m0r = mn0; m1r = mn1;
        float su0 = 0.f, su1 = 0.f;
        #pragma unroll
        for (int j = 0; j < 8; j++) {
            s[j][0] = __expf(s[j][0] - mn0);
            s[j][1] = __expf(s[j][1] - mn0);
            s[j][2] = __expf(s[j][2] - mn1);
            s[j][3] = __expf(s[j][3] - mn1);
            su0 += s[j][0] + s[j][1];
            su1 += s[j][2] + s[j][3];
        }
        su0 += __shfl_xor_sync(0xffffffffu, su0, 1);
        su0 += __shfl_xor_sync(0xffffffffu, su0, 2);
        su1 += __shfl_xor_sync(0xffffffffu, su1, 1);
        su1 += __shfl_xor_sync(0xffffffffu, su1, 2);
        l0r = l0r*a0 + su0;
        l1r = l1r*a1 + su1;
        #pragma unroll
        for (int j = 0; j < 8; j++) {
            o[j][0] *= a0; o[j][1] *= a0; o[j][2] *= a1; o[j][3] *= a1;
        }

        // ---- O += P V ----
        #pragma unroll
        for (int kk = 0; kk < 4; kk++) {
            uint32_t ph[4], pl[4];
            split2(s[2*kk][0],   s[2*kk][1],   ph[0], pl[0]);
            split2(s[2*kk][2],   s[2*kk][3],   ph[1], pl[1]);
            split2(s[2*kk+1][0], s[2*kk+1][1], ph[2], pl[2]);
            split2(s[2*kk+1][2], s[2*kk+1][3], ph[3], pl[3]);
            #pragma unroll
            for (int g = 0; g < 4; g++) {
                uint32_t vhf[4], vlf[4];
                const uint32_t vaddr = sVh + (kk*16 + lrq)*ASTRB + g*32 + lch;
                ldsm4t(vhf, vaddr);
                ldsm4t(vlf, vaddr + AK_SZ);
                mma_bf16(o[2*g],   ph, vhf[0], vhf[1]);
                mma_bf16(o[2*g+1], ph, vhf[2], vhf[3]);
                mma_bf16(o[2*g],   ph, vlf[0], vlf[1]);
                mma_bf16(o[2*g+1], ph, vlf[2], vlf[3]);
                mma_bf16(o[2*g],   pl, vhf[0], vhf[1]);
                mma_bf16(o[2*g+1], pl, vhf[2], vhf[3]);
            }
        }
    }

    // ---- write O into [B,S,D] ----
    const float i0 = 1.f / l0r, i1 = 1.f / l1r;
    const int row0 = qs + wid*16 + (lane >> 2);
    const int row1 = row0 + 8;
    const int b = bh >> 4, h = bh & 15;
    #pragma unroll
    for (int j = 0; j < 8; j++) {
        const int c = h*64 + j*8 + (lane & 3)*2;
        *(float2*)(O + (size_t)(b*SEQ + row0)*D_MODEL + c) =
            make_float2(o[j][0]*i0, o[j][1]*i0);
        *(float2*)(O + (size_t)(b*SEQ + row1)*D_MODEL + c) =
            make_float2(o[j][2]*i1, o[j][3]*i1);
    }
}

// =====================================================================
// launch
// =====================================================================
extern "C" void kernel_launch(void* const* d_in, const int* in_sizes, int n_in,
                              void* d_out, int out_size)
{
    (void)in_sizes; (void)n_in; (void)out_size;
    const float* x  = (const float*)d_in[0];
    const float* Wq = (const float*)d_in[1];
    const float* bq = (const float*)d_in[2];
    const float* Wk = (const float*)d_in[3];
    const float* bk = (const float*)d_in[4];
    const float* Wv = (const float*)d_in[5];
    const float* bv = (const float*)d_in[6];
    const float* Wo = (const float*)d_in[7];
    const float* bo = (const float*)d_in[8];
    float* out = (float*)d_out;

    float *Qp, *Kp, *Vp, *Op;
    cudaGetSymbolAddress((void**)&Qp, g_Q);
    cudaGetSymbolAddress((void**)&Kp, g_K);
    cudaGetSymbolAddress((void**)&Vp, g_V);
    cudaGetSymbolAddress((void**)&Op, g_O);

    cudaFuncSetAttribute(gemm_bf16x3<true>,
                         cudaFuncAttributeMaxDynamicSharedMemorySize, GEMM_SMEM);
    cudaFuncSetAttribute(gemm_bf16x3<false>,
                         cudaFuncAttributeMaxDynamicSharedMemorySize, GEMM_SMEM);
    cudaFuncSetAttribute(attn_mma,
                         cudaFuncAttributeMaxDynamicSharedMemorySize, ATTN_SMEM);

    const dim3 gg(D_MODEL/128, MROWS/128);   // (8, 32)
    gemm_bf16x3<true><<<gg, 256, GEMM_SMEM>>>(x, Wq, bq, Qp);
    gemm_bf16x3<true><<<gg, 256, GEMM_SMEM>>>(x, Wk, bk, Kp);
    gemm_bf16x3<true><<<gg, 256, GEMM_SMEM>>>(x, Wv, bv, Vp);

    const int rthreads = BHTOT * SEQ * 32;
    rope_kernel<<<dim3(rthreads/256, 2), 256>>>(Qp, Kp);

    attn_mma<<<dim3(SEQ/128, BHTOT), 256, ATTN_SMEM>>>(Qp, Kp, Vp, Op);

    gemm_bf16x3<false><<<gg, 256, GEMM_SMEM>>>(Op, Wo, bo, out);
}

// round 4
// speedup vs baseline: 2.7361x; 1.0244x over previous
#include <cuda_runtime.h>
#include <cuda_bf16.h>
#include <math.h>
#include <stdint.h>

#define D_MODEL 1024
#define NHEADS  16
#define DHEAD   64
#define BATCH   2
#define SEQ     2048
#define MROWS   (BATCH*SEQ)          // 4096
#define BHTOT   (BATCH*NHEADS)       // 32
#define DD      (D_MODEL*D_MODEL)

// ---------------- scratch (no allocations allowed) ----------------
__device__ float g_Q[(size_t)BHTOT*SEQ*DHEAD];    // fp32 post-proj (pre-rope)
__device__ float g_K[(size_t)BHTOT*SEQ*DHEAD];
__device__ __nv_bfloat16 g_xh[(size_t)MROWS*D_MODEL], g_xl[(size_t)MROWS*D_MODEL];
__device__ __nv_bfloat16 g_Wh[(size_t)4*DD],          g_Wl[(size_t)4*DD];
__device__ __nv_bfloat16 g_Qh[(size_t)BHTOT*SEQ*DHEAD], g_Ql[(size_t)BHTOT*SEQ*DHEAD];
__device__ __nv_bfloat16 g_Kh[(size_t)BHTOT*SEQ*DHEAD], g_Kl[(size_t)BHTOT*SEQ*DHEAD];
__device__ __nv_bfloat16 g_Vh[(size_t)BHTOT*SEQ*DHEAD], g_Vl[(size_t)BHTOT*SEQ*DHEAD];
__device__ __nv_bfloat16 g_Oh[(size_t)MROWS*D_MODEL],   g_Ol[(size_t)MROWS*D_MODEL];

// =====================================================================
// helpers
// =====================================================================
__device__ __forceinline__ uint32_t smem_u32(const void* p) {
    uint32_t a;
    asm("{ .reg .u64 t; cvta.to.shared.u64 t, %1; cvt.u32.u64 %0, t; }"
        : "=r"(a) : "l"(p));
    return a;
}
__device__ __forceinline__ void ldsm4(uint32_t r[4], uint32_t a) {
    asm volatile("ldmatrix.sync.aligned.m8n8.x4.shared.b16 {%0,%1,%2,%3}, [%4];"
                 : "=r"(r[0]), "=r"(r[1]), "=r"(r[2]), "=r"(r[3]) : "r"(a));
}
__device__ __forceinline__ void ldsm4t(uint32_t r[4], uint32_t a) {
    asm volatile("ldmatrix.sync.aligned.m8n8.x4.trans.shared.b16 {%0,%1,%2,%3}, [%4];"
                 : "=r"(r[0]), "=r"(r[1]), "=r"(r[2]), "=r"(r[3]) : "r"(a));
}
__device__ __forceinline__ void mma_bf16(float d[4], const uint32_t a[4],
                                         uint32_t b0, uint32_t b1) {
    asm volatile(
        "mma.sync.aligned.m16n8k16.row.col.f32.bf16.bf16.f32 "
        "{%0,%1,%2,%3}, {%4,%5,%6,%7}, {%8,%9}, {%0,%1,%2,%3};"
        : "+f"(d[0]), "+f"(d[1]), "+f"(d[2]), "+f"(d[3])
        : "r"(a[0]), "r"(a[1]), "r"(a[2]), "r"(a[3]), "r"(b0), "r"(b1));
}
__device__ __forceinline__ void split2(float v0, float v1, uint32_t& hi, uint32_t& lo) {
    __nv_bfloat16 h0 = __float2bfloat16(v0);
    __nv_bfloat16 h1 = __float2bfloat16(v1);
    __nv_bfloat162 H = __halves2bfloat162(h0, h1);
    hi = *reinterpret_cast<uint32_t*>(&H);
    __nv_bfloat162 L = __floats2bfloat162_rn(v0 - __bfloat162float(h0),
                                             v1 - __bfloat162float(h1));
    lo = *reinterpret_cast<uint32_t*>(&L);
}
#define CPA16(dst, src) \
    asm volatile("cp.async.cg.shared.global [%0], [%1], 16;" \
                 :: "r"(dst), "l"(src) : "memory")
#define CPA_COMMIT() asm volatile("cp.async.commit_group;" ::: "memory")
#define CPA_WAIT0()  asm volatile("cp.async.wait_group 0;" ::: "memory")

// =====================================================================
// split kernel: fp32 -> (bf16 hi, bf16 lo), vectorized x4
// =====================================================================
__global__ void split4_kernel(const float* __restrict__ in,
                              __nv_bfloat16* __restrict__ hi,
                              __nv_bfloat16* __restrict__ lo, int n4)
{
    const int i = blockIdx.x * blockDim.x + threadIdx.x;
    if (i >= n4) return;
    const float4 v = ((const float4*)in)[i];
    uint32_t h0, l0, h1, l1;
    split2(v.x, v.y, h0, l0);
    split2(v.z, v.w, h1, l1);
    ((uint2*)hi)[i] = make_uint2(h0, h1);
    ((uint2*)lo)[i] = make_uint2(l0, l1);
}

// =====================================================================
// GEMM mainloop (shared): C[128,128] tile of A[M,1024] @ W[N,1024]^T
// pre-split bf16 inputs, cp.async double-buffered, BK=32.
// =====================================================================
#define GSTB   80
#define GA_SZ  (128*GSTB)          // 10240
#define GSTAGE (4*GA_SZ)           // 40960
#define GEMM_SMEM (2*GSTAGE)       // 81920

__device__ __forceinline__ void gemm_mainloop(
    const __nv_bfloat16* __restrict__ Ah, const __nv_bfloat16* __restrict__ Al,
    const __nv_bfloat16* __restrict__ Bh, const __nv_bfloat16* __restrict__ Bl,
    int m0, int n0, uint32_t sbase, float acc[2][8][4])
{
    const int tid = threadIdx.x;
    const int lane = tid & 31, wid = tid >> 5;
    const int wm = wid & 3, wn = wid >> 2;
    const uint32_t lrq = (lane & 15);
    const uint32_t lch = ((lane >> 4) << 3) * 2;

    const int c0 = tid * 2;
    const int row0 = c0 >> 2,      col0 = (c0 & 3);
    const int row1 = (c0+1) >> 2,  col1 = ((c0+1) & 3);

    auto issue = [&](int s, int buf) {
        const int k0 = s * 32;
        const uint32_t dst = sbase + buf * GSTAGE;
        {
            const uint32_t d0 = dst + row0*GSTB + col0*16;
            const size_t ea = (size_t)(m0 + row0) * 1024 + k0 + col0*8;
            const size_t eb = (size_t)(n0 + row0) * 1024 + k0 + col0*8;
            CPA16(d0,           Ah + ea);
            CPA16(d0 +   GA_SZ, Al + ea);
            CPA16(d0 + 2*GA_SZ, Bh + eb);
            CPA16(d0 + 3*GA_SZ, Bl + eb);
        }
        {
            const uint32_t d0 = dst + row1*GSTB + col1*16;
            const size_t ea = (size_t)(m0 + row1) * 1024 + k0 + col1*8;
            const size_t eb = (size_t)(n0 + row1) * 1024 + k0 + col1*8;
            CPA16(d0,           Ah + ea);
            CPA16(d0 +   GA_SZ, Al + ea);
            CPA16(d0 + 2*GA_SZ, Bh + eb);
            CPA16(d0 + 3*GA_SZ, Bl + eb);
        }
    };

    issue(0, 0);
    CPA_COMMIT();
    CPA_WAIT0();
    __syncthreads();

    for (int s = 0; s < 32; s++) {
        const int buf = s & 1;
        if (s < 31) { issue(s + 1, buf ^ 1); CPA_COMMIT(); }

        const uint32_t sA = sbase + buf * GSTAGE;
        const uint32_t sB = sA + 2*GA_SZ;
        #pragma unroll
        for (int kk = 0; kk < 2; kk++) {
            uint32_t ah[2][4], al[2][4];
            #pragma unroll
            for (int mi = 0; mi < 2; mi++) {
                const uint32_t addr = sA + (wm*32 + mi*16 + lrq)*GSTB + kk*32 + lch;
                ldsm4(ah[mi], addr);
                ldsm4(al[mi], addr + GA_SZ);
            }
            #pragma unroll
            for (int g = 0; g < 4; g++) {
                uint32_t bh[4], bl[4];
                const uint32_t baddr = sB + (wn*64 + g*16 + lrq)*GSTB + kk*32 + lch;
                ldsm4(bh, baddr);
                ldsm4(bl, baddr + GA_SZ);
                #pragma unroll
                for (int mi = 0; mi < 2; mi++) {
                    mma_bf16(acc[mi][2*g],   ah[mi], bh[0], bh[2]);
                    mma_bf16(acc[mi][2*g+1], ah[mi], bh[1], bh[3]);
                    mma_bf16(acc[mi][2*g],   ah[mi], bl[0], bl[2]);
                    mma_bf16(acc[mi][2*g+1], ah[mi], bl[1], bl[3]);
                    mma_bf16(acc[mi][2*g],   al[mi], bh[0], bh[2]);
                    mma_bf16(acc[mi][2*g+1], al[mi], bh[1], bh[3]);
                }
            }
        }
        if (s < 31) CPA_WAIT0();
        __syncthreads();
    }
}

// =====================================================================
// QKV GEMM: z=0 -> Q fp32 BHSD; z=1 -> K fp32 BHSD; z=2 -> V split bf16 BHSD
// =====================================================================
__global__ __launch_bounds__(256)
void gemm_qkv(const __nv_bfloat16* __restrict__ xh, const __nv_bfloat16* __restrict__ xl,
              const __nv_bfloat16* __restrict__ Wh, const __nv_bfloat16* __restrict__ Wl,
              const float* __restrict__ bQ, const float* __restrict__ bK,
              const float* __restrict__ bV,
              float* __restrict__ Qo, float* __restrict__ Ko,
              __nv_bfloat16* __restrict__ Vh, __nv_bfloat16* __restrict__ Vl)
{
    extern __shared__ char smraw[];
    const uint32_t sbase = smem_u32(smraw);
    const int z = blockIdx.z;
    const int m0 = blockIdx.y * 128, n0 = blockIdx.x * 128;
    const __nv_bfloat16* Whp = Wh + (size_t)z * DD;
    const __nv_bfloat16* Wlp = Wl + (size_t)z * DD;
    const float* bias = (z == 0) ? bQ : (z == 1) ? bK : bV;

    float acc[2][8][4] = {};
    gemm_mainloop(xh, xl, Whp, Wlp, m0, n0, sbase, acc);

    const int lane = threadIdx.x & 31, wid = threadIdx.x >> 5;
    const int wm = wid & 3, wn = wid >> 2;
    const int rbase = m0 + wm*32 + (lane >> 2);
    const int cbase = n0 + wn*64 + (lane & 3)*2;
    float* fout = (z == 0) ? Qo : Ko;

    #pragma unroll
    for (int mi = 0; mi < 2; mi++) {
        #pragma unroll
        for (int j = 0; j < 8; j++) {
            const int c = cbase + j*8;
            const float2 b2 = *(const float2*)(bias + c);
            const int r0 = rbase + mi*16, r1 = r0 + 8;
            const float2 v0 = make_float2(acc[mi][j][0] + b2.x, acc[mi][j][1] + b2.y);
            const float2 v1 = make_float2(acc[mi][j][2] + b2.x, acc[mi][j][3] + b2.y);
            const int h = c >> 6, d = c & 63;
            const int b0b = r0 >> 11, s0 = r0 & (SEQ-1);
            const int b1b = r1 >> 11, s1 = r1 & (SEQ-1);
            const size_t i0 = (((size_t)(b0b*NHEADS + h)*SEQ + s0) << 6) + d;
            const size_t i1 = (((size_t)(b1b*NHEADS + h)*SEQ + s1) << 6) + d;
            if (z < 2) {
                *(float2*)(fout + i0) = v0;
                *(float2*)(fout + i1) = v1;
            } else {
                uint32_t hi, lo;
                split2(v0.x, v0.y, hi, lo);
                *(uint32_t*)(Vh + i0) = hi;
                *(uint32_t*)(Vl + i0) = lo;
                split2(v1.x, v1.y, hi, lo);
                *(uint32_t*)(Vh + i1) = hi;
                *(uint32_t*)(Vl + i1) = lo;
            }
        }
    }
}

// =====================================================================
// Output GEMM: out = O @ Wo^T + bo (fp32 row-major)
// =====================================================================
__global__ __launch_bounds__(256)
void gemm_out(const __nv_bfloat16* __restrict__ Oh, const __nv_bfloat16* __restrict__ Ol,
              const __nv_bfloat16* __restrict__ Wh, const __nv_bfloat16* __restrict__ Wl,
              const float* __restrict__ bias, float* __restrict__ out)
{
    extern __shared__ char smraw[];
    const uint32_t sbase = smem_u32(smraw);
    const int m0 = blockIdx.y * 128, n0 = blockIdx.x * 128;

    float acc[2][8][4] = {};
    gemm_mainloop(Oh, Ol, Wh, Wl, m0, n0, sbase, acc);

    const int lane = threadIdx.x & 31, wid = threadIdx.x >> 5;
    const int wm = wid & 3, wn = wid >> 2;
    const int rbase = m0 + wm*32 + (lane >> 2);
    const int cbase = n0 + wn*64 + (lane & 3)*2;
    #pragma unroll
    for (int mi = 0; mi < 2; mi++) {
        #pragma unroll
        for (int j = 0; j < 8; j++) {
            const int c = cbase + j*8;
            const float2 b2 = *(const float2*)(bias + c);
            const int r0 = rbase + mi*16, r1 = r0 + 8;
            *(float2*)(out + (size_t)r0 * D_MODEL + c) =
                make_float2(acc[mi][j][0] + b2.x, acc[mi][j][1] + b2.y);
            *(float2*)(out + (size_t)r1 * D_MODEL + c) =
                make_float2(acc[mi][j][2] + b2.x, acc[mi][j][3] + b2.y);
        }
    }
}

// =====================================================================
// RoPE + split: fp32 Q/K -> rotated -> bf16 hi/lo
// =====================================================================
__global__ void rope_split(const float* __restrict__ Qf, const float* __restrict__ Kf,
                           __nv_bfloat16* __restrict__ Qh, __nv_bfloat16* __restrict__ Ql,
                           __nv_bfloat16* __restrict__ Kh, __nv_bfloat16* __restrict__ Kl)
{
    const unsigned t = blockIdx.x * blockDim.x + threadIdx.x;
    const int z  = blockIdx.y;
    const float* src = z ? Kf : Qf;
    __nv_bfloat16* Xh = z ? Kh : Qh;
    __nv_bfloat16* Xl = z ? Kl : Ql;

    const int d  = t & 31;
    const int s  = (t >> 5) & (SEQ - 1);
    const int bh = t >> 16;
    const size_t base = ((size_t)bh * SEQ + s) * DHEAD;

    const float inv = exp2f(-(float)d * 0.41524101186091903f);
    const float ang = (float)s * inv;
    float sn, cs;
    sincosf(ang, &sn, &cs);

    const float x1 = src[base + d];
    const float x2 = src[base + d + 32];
    const float y1 = x1 * cs - x2 * sn;
    const float y2 = x2 * cs + x1 * sn;

    const __nv_bfloat16 h1 = __float2bfloat16(y1);
    const __nv_bfloat16 h2 = __float2bfloat16(y2);
    Xh[base + d]      = h1;
    Xh[base + d + 32] = h2;
    Xl[base + d]      = __float2bfloat16(y1 - __bfloat162float(h1));
    Xl[base + d + 32] = __float2bfloat16(y2 - __bfloat162float(h2));
}

// =====================================================================
// Flash attention on pre-split bf16; Q fragments in regs; cp.async KV;
// output written as split bf16 (Oh/Ol). CTA = (bh, 128 q rows).
// =====================================================================
#define ASTRB 144
#define AK_SZ (64*ASTRB)          // 9216 per matrix-half
#define ABUF  (4*AK_SZ)           // 36864 (Kh,Kl,Vh,Vl)
#define ATTN_SMEM (2*ABUF)        // 73728

__global__ __launch_bounds__(256)
void attn_mma(const __nv_bfloat16* __restrict__ Qh_g, const __nv_bfloat16* __restrict__ Ql_g,
              const __nv_bfloat16* __restrict__ Kh_g, const __nv_bfloat16* __restrict__ Kl_g,
              const __nv_bfloat16* __restrict__ Vh_g, const __nv_bfloat16* __restrict__ Vl_g,
              __nv_bfloat16* __restrict__ Oh_g, __nv_bfloat16* __restrict__ Ol_g)
{
    extern __shared__ char sm[];
    const uint32_t sbase = smem_u32(sm);
    const int tid = threadIdx.x, wid = tid >> 5, lane = tid & 31;
    const int qb  = gridDim.x - 1 - blockIdx.x;
    const int bh  = blockIdx.y;
    const int qs  = qb * 128;

    const size_t bhoff = (size_t)bh * SEQ * DHEAD;
    const __nv_bfloat16* Khp = Kh_g + bhoff;
    const __nv_bfloat16* Klp = Kl_g + bhoff;
    const __nv_bfloat16* Vhp = Vh_g + bhoff;
    const __nv_bfloat16* Vlp = Vl_g + bhoff;

    const uint32_t lrq = (lane & 15);
    const uint32_t lch = ((lane >> 4) << 3) * 2;

    // ---- Q fragments direct from global (mma A-fragment lane map) ----
    uint32_t qh[4][4], ql[4][4];
    {
        const __nv_bfloat16* Qhp = Qh_g + bhoff;
        const __nv_bfloat16* Qlp = Ql_g + bhoff;
        const int r0 = qs + wid*16 + (lane >> 2);
        const int cq = (lane & 3) * 2;
        #pragma unroll
        for (int kk = 0; kk < 4; kk++) {
            const int c = kk*16 + cq;
            const size_t e00 = (size_t)r0 * 64 + c;
            const size_t e10 = (size_t)(r0 + 8) * 64 + c;
            qh[kk][0] = *(const uint32_t*)(Qhp + e00);
            qh[kk][1] = *(const uint32_t*)(Qhp + e10);
            qh[kk][2] = *(const uint32_t*)(Qhp + e00 + 8);
            qh[kk][3] = *(const uint32_t*)(Qhp + e10 + 8);
            ql[kk][0] = *(const uint32_t*)(Qlp + e00);
            ql[kk][1] = *(const uint32_t*)(Qlp + e10);
            ql[kk][2] = *(const uint32_t*)(Qlp + e00 + 8);
            ql[kk][3] = *(const uint32_t*)(Qlp + e10 + 8);
        }
    }

    // KV loader chunk map (2 chunks of 16B per thread per matrix-half)
    const int ch0 = tid*2, ch1 = tid*2 + 1;
    const int kr0 = ch0 >> 3, kc0 = ch0 & 7;
    const int kr1 = ch1 >> 3, kc1 = ch1 & 7;

    auto issueKV = [&](int t, int buf) {
        const int ks = t * 64;
        const uint32_t dst = sbase + buf * ABUF;
        {
            const uint32_t d0 = dst + kr0*ASTRB + kc0*16;
            const size_t  s0 = ((size_t)(ks + kr0)) * 64 + kc0*8;
            CPA16(d0,           Khp + s0);
            CPA16(d0 +   AK_SZ, Klp + s0);
            CPA16(d0 + 2*AK_SZ, Vhp + s0);
            CPA16(d0 + 3*AK_SZ, Vlp + s0);
        }
        {
            const uint32_t d0 = dst + kr1*ASTRB + kc1*16;
            const size_t  s0 = ((size_t)(ks + kr1)) * 64 + kc1*8;
            CPA16(d0,           Khp + s0);
            CPA16(d0 +   AK_SZ, Klp + s0);
            CPA16(d0 + 2*AK_SZ, Vhp + s0);
            CPA16(d0 + 3*AK_SZ, Vlp + s0);
        }
    };

    float o[8][4] = {};
    float m0r = -1e30f, m1r = -1e30f, l0r = 0.f, l1r = 0.f;
    const int nt = 2*(qb + 1);

    issueKV(0, 0);
    CPA_COMMIT();
    CPA_WAIT0();
    __syncthreads();

    for (int t = 0; t < nt; t++) {
        const int buf = t & 1;
        const int ks  = t * 64;
        if (t + 1 < nt) { issueKV(t + 1, buf ^ 1); CPA_COMMIT(); }

        if (qs + wid*16 + 15 >= ks) {
            const uint32_t sKh = sbase + buf * ABUF;
            const uint32_t sVh = sKh + 2*AK_SZ;

            // ---- S = Q K^T ----
            float s[8][4] = {};
            #pragma unroll
            for (int kk = 0; kk < 4; kk++) {
                #pragma unroll
                for (int g = 0; g < 4; g++) {
                    uint32_t khf[4], klf[4];
                    const uint32_t kaddr = sKh + (g*16 + lrq)*ASTRB + kk*32 + lch;
                    ldsm4(khf, kaddr);
                    ldsm4(klf, kaddr + AK_SZ);
                    mma_bf16(s[2*g],   qh[kk], khf[0], khf[2]);
                    mma_bf16(s[2*g+1], qh[kk], khf[1], khf[3]);
                    mma_bf16(s[2*g],   qh[kk], klf[0], klf[2]);
                    mma_bf16(s[2*g+1], qh[kk], klf[1], klf[3]);
                    mma_bf16(s[2*g],   ql[kk], khf[0], khf[2]);
                    mma_bf16(s[2*g+1], ql[kk], khf[1], khf[3]);
                }
            }

            // ---- scale + causal mask ----
            const int r0 = qs + wid*16 + (lane >> 2);
            const int r1 = r0 + 8;
            const float SC = 0.125f;
            if (ks + 63 > qs + wid*16) {
                #pragma unroll
                for (int j = 0; j < 8; j++) {
                    const int c = ks + j*8 + (lane & 3)*2;
                    s[j][0] = (c     <= r0) ? s[j][0]*SC : -1e30f;
                    s[j][1] = (c + 1 <= r0) ? s[j][1]*SC : -1e30f;
                    s[j][2] = (c     <= r1) ? s[j][2]*SC : -1e30f;
                    s[j][3] = (c + 1 <= r1) ? s[j][3]*SC : -1e30f;
                }
            } else {
                #pragma unroll
                for (int j = 0; j < 8; j++) {
                    s[j][0] *= SC; s[j][1] *= SC; s[j][2] *= SC; s[j][3] *= SC;
                }
            }

            // ---- online softmax ----
            float mx0 = -1e30f, mx1 = -1e30f;
            #pragma unroll
            for (int j = 0; j < 8; j++) {
                mx0 = fmaxf(mx0, fmaxf(s[j][0], s[j][1]));
                mx1 = fmaxf(mx1, fmaxf(s[j][2], s[j][3]));
            }
            mx0 = fmaxf(mx0, __shfl_xor_sync(0xffffffffu, mx0, 1));
            mx0 = fmaxf(mx0, __shfl_xor_sync(0xffffffffu, mx0, 2));
            mx1 = fmaxf(mx1, __shfl_xor_sync(0xffffffffu, mx1, 1));
            mx1 = fmaxf(mx1, __shfl_xor_sync(0xffffffffu, mx1, 2));
            const float mn0 = fmaxf(m0r, mx0), mn1 = fmaxf(m1r, mx1);
            const float a0 = __expf(m0r - mn0), a1 = __expf(m1r - mn1);
            m0r = mn0; m1r = mn1;
            float su0 = 0.f, su1 = 0.f;
            #pragma unroll
            for (int j = 0; j < 8; j++) {
                s[j][0] = __expf(s[j][0] - mn0);
                s[j][1] = __expf(s[j][1] - mn0);
                s[j][2] = __expf(s[j][2] - mn1);
                s[j][3] = __expf(s[j][3] - mn1);
                su0 += s[j][0] + s[j][1];
                su1 += s[j][2] + s[j][3];
            }
            su0 += __shfl_xor_sync(0xffffffffu, su0, 1);
            su0 += __shfl_xor_sync(0xffffffffu, su0, 2);
            su1 += __shfl_xor_sync(0xffffffffu, su1, 1);
            su1 += __shfl_xor_sync(0xffffffffu, su1, 2);
            l0r = l0r*a0 + su0;
            l1r = l1r*a1 + su1;
            #pragma unroll
            for (int j = 0; j < 8; j++) {
                o[j][0] *= a0; o[j][1] *= a0; o[j][2] *= a1; o[j][3] *= a1;
            }

            // ---- O += P V ----
            #pragma unroll
            for (int kk = 0; kk < 4; kk++) {
                uint32_t ph[4], pl[4];
                split2(s[2*kk][0],   s[2*kk][1],   ph[0], pl[0]);
                split2(s[2*kk][2],   s[2*kk][3],   ph[1], pl[1]);
                split2(s[2*kk+1][0], s[2*kk+1][1], ph[2], pl[2]);
                split2(s[2*kk+1][2], s[2*kk+1][3], ph[3], pl[3]);
                #pragma unroll
                for (int g = 0; g < 4; g++) {
                    uint32_t vhf[4], vlf[4];
                    const uint32_t vaddr = sVh + (kk*16 + lrq)*ASTRB + g*32 + lch;
                    ldsm4t(vhf, vaddr);
                    ldsm4t(vlf, vaddr + AK_SZ);
                    mma_bf16(o[2*g],   ph, vhf[0], vhf[1]);
                    mma_bf16(o[2*g+1], ph, vhf[2], vhf[3]);
                    mma_bf16(o[2*g],   ph, vlf[0], vlf[1]);
                    mma_bf16(o[2*g+1], ph, vlf[2], vlf[3]);
                    mma_bf16(o[2*g],   pl, vhf[0], vhf[1]);
                    mma_bf16(o[2*g+1], pl, vhf[2], vhf[3]);
                }
            }
        }

        if (t + 1 < nt) CPA_WAIT0();
        __syncthreads();
    }

    // ---- write O split bf16 into [B,S,D] ----
    const float i0 = 1.f / l0r, i1 = 1.f / l1r;
    const int row0 = qs + wid*16 + (lane >> 2);
    const int row1 = row0 + 8;
    const int b = bh >> 4, h = bh & 15;
    #pragma unroll
    for (int j = 0; j < 8; j++) {
        const int c = h*64 + j*8 + (lane & 3)*2;
        const size_t e0 = (size_t)(b*SEQ + row0)*D_MODEL + c;
        const size_t e1 = (size_t)(b*SEQ + row1)*D_MODEL + c;
        uint32_t hi, lo;
        split2(o[j][0]*i0, o[j][1]*i0, hi, lo);
        *(uint32_t*)(Oh_g + e0) = hi;
        *(uint32_t*)(Ol_g + e0) = lo;
        split2(o[j][2]*i1, o[j][3]*i1, hi, lo);
        *(uint32_t*)(Oh_g + e1) = hi;
        *(uint32_t*)(Ol_g + e1) = lo;
    }
}

// =====================================================================
// launch
// =====================================================================
extern "C" void kernel_launch(void* const* d_in, const int* in_sizes, int n_in,
                              void* d_out, int out_size)
{
    (void)in_sizes; (void)n_in; (void)out_size;
    const float* x  = (const float*)d_in[0];
    const float* Wq = (const float*)d_in[1];
    const float* bq = (const float*)d_in[2];
    const float* Wk = (const float*)d_in[3];
    const float* bk = (const float*)d_in[4];
    const float* Wv = (const float*)d_in[5];
    const float* bv = (const float*)d_in[6];
    const float* Wo = (const float*)d_in[7];
    const float* bo = (const float*)d_in[8];
    float* out = (float*)d_out;

    float *Qp, *Kp;
    __nv_bfloat16 *xh, *xl, *Wh, *Wl, *Qh, *Ql, *Kh, *Kl, *Vh, *Vl, *Oh, *Ol;
    cudaGetSymbolAddress((void**)&Qp, g_Q);
    cudaGetSymbolAddress((void**)&Kp, g_K);
    cudaGetSymbolAddress((void**)&xh, g_xh);
    cudaGetSymbolAddress((void**)&xl, g_xl);
    cudaGetSymbolAddress((void**)&Wh, g_Wh);
    cudaGetSymbolAddress((void**)&Wl, g_Wl);
    cudaGetSymbolAddress((void**)&Qh, g_Qh);
    cudaGetSymbolAddress((void**)&Ql, g_Ql);
    cudaGetSymbolAddress((void**)&Kh, g_Kh);
    cudaGetSymbolAddress((void**)&Kl, g_Kl);
    cudaGetSymbolAddress((void**)&Vh, g_Vh);
    cudaGetSymbolAddress((void**)&Vl, g_Vl);
    cudaGetSymbolAddress((void**)&Oh, g_Oh);
    cudaGetSymbolAddress((void**)&Ol, g_Ol);

    cudaFuncSetAttribute(gemm_qkv,
                         cudaFuncAttributeMaxDynamicSharedMemorySize, GEMM_SMEM);
    cudaFuncSetAttribute(gemm_out,
                         cudaFuncAttributeMaxDynamicSharedMemorySize, GEMM_SMEM);
    cudaFuncSetAttribute(attn_mma,
                         cudaFuncAttributeMaxDynamicSharedMemorySize, ATTN_SMEM);

    // --- precompute splits ---
    split4_kernel<<<(MROWS*D_MODEL/4 + 255)/256, 256>>>(x,  xh, xl, MROWS*D_MODEL/4);
    split4_kernel<<<(DD/4 + 255)/256, 256>>>(Wq, Wh,        Wl,        DD/4);
    split4_kernel<<<(DD/4 + 255)/256, 256>>>(Wk, Wh + DD,   Wl + DD,   DD/4);
    split4_kernel<<<(DD/4 + 255)/256, 256>>>(Wv, Wh + 2*DD, Wl + 2*DD, DD/4);
    split4_kernel<<<(DD/4 + 255)/256, 256>>>(Wo, Wh + 3*DD, Wl + 3*DD, DD/4);

    // --- QKV projections (one launch, z in {Q,K,V}) ---
    gemm_qkv<<<dim3(D_MODEL/128, MROWS/128, 3), 256, GEMM_SMEM>>>(
        xh, xl, Wh, Wl, bq, bk, bv, Qp, Kp, Vh, Vl);

    // --- RoPE + split Q,K ---
    const int rthreads = BHTOT * SEQ * 32;
    rope_split<<<dim3(rthreads/256, 2), 256>>>(Qp, Kp, Qh, Ql, Kh, Kl);

    // --- attention ---
    attn_mma<<<dim3(SEQ/128, BHTOT), 256, ATTN_SMEM>>>(
        Qh, Ql, Kh, Kl, Vh, Vl, Oh, Ol);

    // --- output projection ---
    gemm_out<<<dim3(D_MODEL/128, MROWS/128), 256, GEMM_SMEM>>>(
        Oh, Ol, Wh + 3*DD, Wl + 3*DD, bo, out);
}

// round 5
// speedup vs baseline: 2.7862x; 1.0183x over previous
#include <cuda_runtime.h>
#include <cuda_bf16.h>
#include <math.h>
#include <stdint.h>

#define D_MODEL 1024
#define NHEADS  16
#define DHEAD   64
#define BATCH   2
#define SEQ     2048
#define MROWS   (BATCH*SEQ)          // 4096
#define BHTOT   (BATCH*NHEADS)       // 32
#define DD      (D_MODEL*D_MODEL)

// ---------------- scratch (no allocations allowed) ----------------
__device__ __nv_bfloat16 g_xh[(size_t)MROWS*D_MODEL], g_xl[(size_t)MROWS*D_MODEL];
__device__ __nv_bfloat16 g_Wh[(size_t)4*DD],          g_Wl[(size_t)4*DD];
__device__ __nv_bfloat16 g_Qh[(size_t)BHTOT*SEQ*DHEAD], g_Ql[(size_t)BHTOT*SEQ*DHEAD];
__device__ __nv_bfloat16 g_Kh[(size_t)BHTOT*SEQ*DHEAD], g_Kl[(size_t)BHTOT*SEQ*DHEAD];
__device__ __nv_bfloat16 g_Vh[(size_t)BHTOT*SEQ*DHEAD], g_Vl[(size_t)BHTOT*SEQ*DHEAD];
__device__ __nv_bfloat16 g_Oh[(size_t)MROWS*D_MODEL],   g_Ol[(size_t)MROWS*D_MODEL];

// =====================================================================
// helpers
// =====================================================================
__device__ __forceinline__ uint32_t smem_u32(const void* p) {
    uint32_t a;
    asm("{ .reg .u64 t; cvta.to.shared.u64 t, %1; cvt.u32.u64 %0, t; }"
        : "=r"(a) : "l"(p));
    return a;
}
__device__ __forceinline__ void ldsm4(uint32_t r[4], uint32_t a) {
    asm volatile("ldmatrix.sync.aligned.m8n8.x4.shared.b16 {%0,%1,%2,%3}, [%4];"
                 : "=r"(r[0]), "=r"(r[1]), "=r"(r[2]), "=r"(r[3]) : "r"(a));
}
__device__ __forceinline__ void ldsm4t(uint32_t r[4], uint32_t a) {
    asm volatile("ldmatrix.sync.aligned.m8n8.x4.trans.shared.b16 {%0,%1,%2,%3}, [%4];"
                 : "=r"(r[0]), "=r"(r[1]), "=r"(r[2]), "=r"(r[3]) : "r"(a));
}
__device__ __forceinline__ void mma_bf16(float d[4], const uint32_t a[4],
                                         uint32_t b0, uint32_t b1) {
    asm volatile(
        "mma.sync.aligned.m16n8k16.row.col.f32.bf16.bf16.f32 "
        "{%0,%1,%2,%3}, {%4,%5,%6,%7}, {%8,%9}, {%0,%1,%2,%3};"
        : "+f"(d[0]), "+f"(d[1]), "+f"(d[2]), "+f"(d[3])
        : "r"(a[0]), "r"(a[1]), "r"(a[2]), "r"(a[3]), "r"(b0), "r"(b1));
}
__device__ __forceinline__ void split2(float v0, float v1, uint32_t& hi, uint32_t& lo) {
    __nv_bfloat16 h0 = __float2bfloat16(v0);
    __nv_bfloat16 h1 = __float2bfloat16(v1);
    __nv_bfloat162 H = __halves2bfloat162(h0, h1);
    hi = *reinterpret_cast<uint32_t*>(&H);
    __nv_bfloat162 L = __floats2bfloat162_rn(v0 - __bfloat162float(h0),
                                             v1 - __bfloat162float(h1));
    lo = *reinterpret_cast<uint32_t*>(&L);
}
#define CPA16(dst, src) \
    asm volatile("cp.async.cg.shared.global [%0], [%1], 16;" \
                 :: "r"(dst), "l"(src) : "memory")
#define CPA_COMMIT() asm volatile("cp.async.commit_group;" ::: "memory")
#define CPA_WAIT0()  asm volatile("cp.async.wait_group 0;" ::: "memory")

// =====================================================================
// split kernels: fp32 -> (bf16 hi, bf16 lo), vectorized x4
// =====================================================================
__global__ void split4_kernel(const float* __restrict__ in,
                              __nv_bfloat16* __restrict__ hi,
                              __nv_bfloat16* __restrict__ lo, int n4)
{
    const int i = blockIdx.x * blockDim.x + threadIdx.x;
    if (i >= n4) return;
    const float4 v = ((const float4*)in)[i];
    uint32_t h0, l0, h1, l1;
    split2(v.x, v.y, h0, l0);
    split2(v.z, v.w, h1, l1);
    ((uint2*)hi)[i] = make_uint2(h0, h1);
    ((uint2*)lo)[i] = make_uint2(l0, l1);
}

__global__ void splitW_kernel(const float* __restrict__ W0, const float* __restrict__ W1,
                              const float* __restrict__ W2, const float* __restrict__ W3,
                              __nv_bfloat16* __restrict__ hi, __nv_bfloat16* __restrict__ lo)
{
    const int z = blockIdx.y;
    const float* in = (z == 0) ? W0 : (z == 1) ? W1 : (z == 2) ? W2 : W3;
    const size_t off4 = ((size_t)z * DD) / 4;
    const int i = blockIdx.x * blockDim.x + threadIdx.x;   // < DD/4
    const float4 v = ((const float4*)in)[i];
    uint32_t h0, l0, h1, l1;
    split2(v.x, v.y, h0, l0);
    split2(v.z, v.w, h1, l1);
    ((uint2*)hi)[off4 + i] = make_uint2(h0, h1);
    ((uint2*)lo)[off4 + i] = make_uint2(l0, l1);
}

// =====================================================================
// GEMM mainloop (shared): C[128,128] tile of A[M,1024] @ W[N,1024]^T
// pre-split bf16 inputs, cp.async double-buffered, BK=32.
// =====================================================================
#define GSTB   80
#define GA_SZ  (128*GSTB)          // 10240
#define GSTAGE (4*GA_SZ)           // 40960
#define GEMM_SMEM (2*GSTAGE)       // 81920

__device__ __forceinline__ void gemm_mainloop(
    const __nv_bfloat16* __restrict__ Ah, const __nv_bfloat16* __restrict__ Al,
    const __nv_bfloat16* __restrict__ Bh, const __nv_bfloat16* __restrict__ Bl,
    int m0, int n0, uint32_t sbase, float acc[2][8][4])
{
    const int tid = threadIdx.x;
    const int lane = tid & 31, wid = tid >> 5;
    const int wm = wid & 3, wn = wid >> 2;
    const uint32_t lrq = (lane & 15);
    const uint32_t lch = ((lane >> 4) << 3) * 2;

    const int c0 = tid * 2;
    const int row0 = c0 >> 2,      col0 = (c0 & 3);
    const int row1 = (c0+1) >> 2,  col1 = ((c0+1) & 3);

    auto issue = [&](int s, int buf) {
        const int k0 = s * 32;
        const uint32_t dst = sbase + buf * GSTAGE;
        {
            const uint32_t d0 = dst + row0*GSTB + col0*16;
            const size_t ea = (size_t)(m0 + row0) * 1024 + k0 + col0*8;
            const size_t eb = (size_t)(n0 + row0) * 1024 + k0 + col0*8;
            CPA16(d0,           Ah + ea);
            CPA16(d0 +   GA_SZ, Al + ea);
            CPA16(d0 + 2*GA_SZ, Bh + eb);
            CPA16(d0 + 3*GA_SZ, Bl + eb);
        }
        {
            const uint32_t d0 = dst + row1*GSTB + col1*16;
            const size_t ea = (size_t)(m0 + row1) * 1024 + k0 + col1*8;
            const size_t eb = (size_t)(n0 + row1) * 1024 + k0 + col1*8;
            CPA16(d0,           Ah + ea);
            CPA16(d0 +   GA_SZ, Al + ea);
            CPA16(d0 + 2*GA_SZ, Bh + eb);
            CPA16(d0 + 3*GA_SZ, Bl + eb);
        }
    };

    issue(0, 0);
    CPA_COMMIT();
    CPA_WAIT0();
    __syncthreads();

    for (int s = 0; s < 32; s++) {
        const int buf = s & 1;
        if (s < 31) { issue(s + 1, buf ^ 1); CPA_COMMIT(); }

        const uint32_t sA = sbase + buf * GSTAGE;
        const uint32_t sB = sA + 2*GA_SZ;
        #pragma unroll
        for (int kk = 0; kk < 2; kk++) {
            uint32_t ah[2][4], al[2][4];
            #pragma unroll
            for (int mi = 0; mi < 2; mi++) {
                const uint32_t addr = sA + (wm*32 + mi*16 + lrq)*GSTB + kk*32 + lch;
                ldsm4(ah[mi], addr);
                ldsm4(al[mi], addr + GA_SZ);
            }
            #pragma unroll
            for (int g = 0; g < 4; g++) {
                uint32_t bh[4], bl[4];
                const uint32_t baddr = sB + (wn*64 + g*16 + lrq)*GSTB + kk*32 + lch;
                ldsm4(bh, baddr);
                ldsm4(bl, baddr + GA_SZ);
                #pragma unroll
                for (int mi = 0; mi < 2; mi++) {
                    mma_bf16(acc[mi][2*g],   ah[mi], bh[0], bh[2]);
                    mma_bf16(acc[mi][2*g+1], ah[mi], bh[1], bh[3]);
                    mma_bf16(acc[mi][2*g],   ah[mi], bl[0], bl[2]);
                    mma_bf16(acc[mi][2*g+1], ah[mi], bl[1], bl[3]);
                    mma_bf16(acc[mi][2*g],   al[mi], bh[0], bh[2]);
                    mma_bf16(acc[mi][2*g+1], al[mi], bh[1], bh[3]);
                }
            }
        }
        if (s < 31) CPA_WAIT0();
        __syncthreads();
    }
}

// =====================================================================
// QKV GEMM:
//   z=0 -> Q: rope applied in-register, written as split bf16 [B,H,S,Dh]
//   z=1 -> K: same
//   z=2 -> V: split bf16 [B,H,S,Dh]
// =====================================================================
#define ROPE_L2B 0.41524101186091903f   // log2(10000)/32

__global__ __launch_bounds__(256)
void gemm_qkv(const __nv_bfloat16* __restrict__ xh, const __nv_bfloat16* __restrict__ xl,
              const __nv_bfloat16* __restrict__ Wh, const __nv_bfloat16* __restrict__ Wl,
              const float* __restrict__ bQ, const float* __restrict__ bK,
              const float* __restrict__ bV,
              __nv_bfloat16* __restrict__ Qh, __nv_bfloat16* __restrict__ Ql,
              __nv_bfloat16* __restrict__ Kh, __nv_bfloat16* __restrict__ Kl,
              __nv_bfloat16* __restrict__ Vh, __nv_bfloat16* __restrict__ Vl)
{
    extern __shared__ char smraw[];
    const uint32_t sbase = smem_u32(smraw);
    const int z = blockIdx.z;
    const int m0 = blockIdx.y * 128, n0 = blockIdx.x * 128;
    const __nv_bfloat16* Whp = Wh + (size_t)z * DD;
    const __nv_bfloat16* Wlp = Wl + (size_t)z * DD;
    const float* bias = (z == 0) ? bQ : (z == 1) ? bK : bV;

    float acc[2][8][4] = {};
    gemm_mainloop(xh, xl, Whp, Wlp, m0, n0, sbase, acc);

    const int lane = threadIdx.x & 31, wid = threadIdx.x >> 5;
    const int wm = wid & 3, wn = wid >> 2;
    const int rbase = m0 + wm*32 + (lane >> 2);
    const int cbase = n0 + wn*64 + (lane & 3)*2;

    if (z == 2) {
        // ---- V: plain bias + split ----
        #pragma unroll
        for (int mi = 0; mi < 2; mi++) {
            #pragma unroll
            for (int j = 0; j < 8; j++) {
                const int c = cbase + j*8;
                const float2 b2 = *(const float2*)(bias + c);
                const int r0 = rbase + mi*16, r1 = r0 + 8;
                const int h = c >> 6, d = c & 63;
                const int b0b = r0 >> 11, s0 = r0 & (SEQ-1);
                const int b1b = r1 >> 11, s1 = r1 & (SEQ-1);
                const size_t i0 = (((size_t)(b0b*NHEADS + h)*SEQ + s0) << 6) + d;
                const size_t i1 = (((size_t)(b1b*NHEADS + h)*SEQ + s1) << 6) + d;
                uint32_t hi, lo;
                split2(acc[mi][j][0] + b2.x, acc[mi][j][1] + b2.y, hi, lo);
                *(uint32_t*)(Vh + i0) = hi;
                *(uint32_t*)(Vl + i0) = lo;
                split2(acc[mi][j][2] + b2.x, acc[mi][j][3] + b2.y, hi, lo);
                *(uint32_t*)(Vh + i1) = hi;
                *(uint32_t*)(Vl + i1) = lo;
            }
        }
    } else {
        // ---- Q/K: in-register RoPE, then split ----
        // Thread owns cols c (reg j, d = c&63 in [0,32)) and c+32 (reg j+4).
        __nv_bfloat16* Xh = (z == 0) ? Qh : Kh;
        __nv_bfloat16* Xl = (z == 0) ? Ql : Kl;
        #pragma unroll
        for (int mi = 0; mi < 2; mi++) {
            #pragma unroll
            for (int rr = 0; rr < 2; rr++) {
                const int r  = rbase + mi*16 + rr*8;
                const int ss = r & (SEQ-1);
                const int bb = r >> 11;
                const float sf = (float)ss;
                #pragma unroll
                for (int j = 0; j < 4; j++) {
                    const int c = cbase + j*8;
                    const int h = c >> 6;
                    const int d = c & 63;           // in [0,32)
                    const float a  = acc[mi][j][rr*2+0]   + bias[c];
                    const float b  = acc[mi][j][rr*2+1]   + bias[c+1];
                    const float pa = acc[mi][j+4][rr*2+0] + bias[c+32];
                    const float pb = acc[mi][j+4][rr*2+1] + bias[c+33];
                    float s0, c0, s1, c1;
                    sincosf(sf * exp2f(-(float)d       * ROPE_L2B), &s0, &c0);
                    sincosf(sf * exp2f(-(float)(d + 1) * ROPE_L2B), &s1, &c1);
                    const float ya = a*c0  - pa*s0, yb = b*c1  - pb*s1;
                    const float za = pa*c0 + a*s0,  zb = pb*c1 + b*s1;
                    const size_t base = (((size_t)(bb*NHEADS + h)*SEQ + ss) << 6) + d;
                    uint32_t hi, lo;
                    split2(ya, yb, hi, lo);
                    *(uint32_t*)(Xh + base) = hi;
                    *(uint32_t*)(Xl + base) = lo;
                    split2(za, zb, hi, lo);
                    *(uint32_t*)(Xh + base + 32) = hi;
                    *(uint32_t*)(Xl + base + 32) = lo;
                }
            }
        }
    }
}

// =====================================================================
// Output GEMM: out = O @ Wo^T + bo (fp32 row-major)
// =====================================================================
__global__ __launch_bounds__(256)
void gemm_out(const __nv_bfloat16* __restrict__ Oh, const __nv_bfloat16* __restrict__ Ol,
              const __nv_bfloat16* __restrict__ Wh, const __nv_bfloat16* __restrict__ Wl,
              const float* __restrict__ bias, float* __restrict__ out)
{
    extern __shared__ char smraw[];
    const uint32_t sbase = smem_u32(smraw);
    const int m0 = blockIdx.y * 128, n0 = blockIdx.x * 128;

    float acc[2][8][4] = {};
    gemm_mainloop(Oh, Ol, Wh, Wl, m0, n0, sbase, acc);

    const int lane = threadIdx.x & 31, wid = threadIdx.x >> 5;
    const int wm = wid & 3, wn = wid >> 2;
    const int rbase = m0 + wm*32 + (lane >> 2);
    const int cbase = n0 + wn*64 + (lane & 3)*2;
    #pragma unroll
    for (int mi = 0; mi < 2; mi++) {
        #pragma unroll
        for (int j = 0; j < 8; j++) {
            const int c = cbase + j*8;
            const float2 b2 = *(const float2*)(bias + c);
            const int r0 = rbase + mi*16, r1 = r0 + 8;
            *(float2*)(out + (size_t)r0 * D_MODEL + c) =
                make_float2(acc[mi][j][0] + b2.x, acc[mi][j][1] + b2.y);
            *(float2*)(out + (size_t)r1 * D_MODEL + c) =
                make_float2(acc[mi][j][2] + b2.x, acc[mi][j][3] + b2.y);
        }
    }
}

// =====================================================================
// Flash attention on pre-split bf16; Q fragments in regs; cp.async KV;
// output written as split bf16 (Oh/Ol). CTA = (bh, 128 q rows).
// =====================================================================
#define ASTRB 144
#define AK_SZ (64*ASTRB)          // 9216 per matrix-half
#define ABUF  (4*AK_SZ)           // 36864 (Kh,Kl,Vh,Vl)
#define ATTN_SMEM (2*ABUF)        // 73728

__global__ __launch_bounds__(256)
void attn_mma(const __nv_bfloat16* __restrict__ Qh_g, const __nv_bfloat16* __restrict__ Ql_g,
              const __nv_bfloat16* __restrict__ Kh_g, const __nv_bfloat16* __restrict__ Kl_g,
              const __nv_bfloat16* __restrict__ Vh_g, const __nv_bfloat16* __restrict__ Vl_g,
              __nv_bfloat16* __restrict__ Oh_g, __nv_bfloat16* __restrict__ Ol_g)
{
    extern __shared__ char sm[];
    const uint32_t sbase = smem_u32(sm);
    const int tid = threadIdx.x, wid = tid >> 5, lane = tid & 31;
    const int qb  = gridDim.x - 1 - blockIdx.x;
    const int bh  = blockIdx.y;
    const int qs  = qb * 128;

    const size_t bhoff = (size_t)bh * SEQ * DHEAD;
    const __nv_bfloat16* Khp = Kh_g + bhoff;
    const __nv_bfloat16* Klp = Kl_g + bhoff;
    const __nv_bfloat16* Vhp = Vh_g + bhoff;
    const __nv_bfloat16* Vlp = Vl_g + bhoff;

    const uint32_t lrq = (lane & 15);
    const uint32_t lch = ((lane >> 4) << 3) * 2;

    // ---- Q fragments direct from global (mma A-fragment lane map) ----
    uint32_t qh[4][4], ql[4][4];
    {
        const __nv_bfloat16* Qhp = Qh_g + bhoff;
        const __nv_bfloat16* Qlp = Ql_g + bhoff;
        const int r0 = qs + wid*16 + (lane >> 2);
        const int cq = (lane & 3) * 2;
        #pragma unroll
        for (int kk = 0; kk < 4; kk++) {
            const int c = kk*16 + cq;
            const size_t e00 = (size_t)r0 * 64 + c;
            const size_t e10 = (size_t)(r0 + 8) * 64 + c;
            qh[kk][0] = *(const uint32_t*)(Qhp + e00);
            qh[kk][1] = *(const uint32_t*)(Qhp + e10);
            qh[kk][2] = *(const uint32_t*)(Qhp + e00 + 8);
            qh[kk][3] = *(const uint32_t*)(Qhp + e10 + 8);
            ql[kk][0] = *(const uint32_t*)(Qlp + e00);
            ql[kk][1] = *(const uint32_t*)(Qlp + e10);
            ql[kk][2] = *(const uint32_t*)(Qlp + e00 + 8);
            ql[kk][3] = *(const uint32_t*)(Qlp + e10 + 8);
        }
    }

    // KV loader chunk map
    const int ch0 = tid*2, ch1 = tid*2 + 1;
    const int kr0 = ch0 >> 3, kc0 = ch0 & 7;
    const int kr1 = ch1 >> 3, kc1 = ch1 & 7;

    auto issueKV = [&](int t, int buf) {
        const int ks = t * 64;
        const uint32_t dst = sbase + buf * ABUF;
        {
            const uint32_t d0 = dst + kr0*ASTRB + kc0*16;
            const size_t  s0 = ((size_t)(ks + kr0)) * 64 + kc0*8;
            CPA16(d0,           Khp + s0);
            CPA16(d0 +   AK_SZ, Klp + s0);
            CPA16(d0 + 2*AK_SZ, Vhp + s0);
            CPA16(d0 + 3*AK_SZ, Vlp + s0);
        }
        {
            const uint32_t d0 = dst + kr1*ASTRB + kc1*16;
            const size_t  s0 = ((size_t)(ks + kr1)) * 64 + kc1*8;
            CPA16(d0,           Khp + s0);
            CPA16(d0 +   AK_SZ, Klp + s0);
            CPA16(d0 + 2*AK_SZ, Vhp + s0);
            CPA16(d0 + 3*AK_SZ, Vlp + s0);
        }
    };

    float o[8][4] = {};
    float m0r = -1e30f, m1r = -1e30f, l0r = 0.f, l1r = 0.f;
    const int nt = 2*(qb + 1);

    issueKV(0, 0);
    CPA_COMMIT();
    CPA_WAIT0();
    __syncthreads();

    for (int t = 0; t < nt; t++) {
        const int buf = t & 1;
        const int ks  = t * 64;
        if (t + 1 < nt) { issueKV(t + 1, buf ^ 1); CPA_COMMIT(); }

        if (qs + wid*16 + 15 >= ks) {
            const uint32_t sKh = sbase + buf * ABUF;
            const uint32_t sVh = sKh + 2*AK_SZ;

            // ---- S = Q K^T ----
            float s[8][4] = {};
            #pragma unroll
            for (int kk = 0; kk < 4; kk++) {
                #pragma unroll
                for (int g = 0; g < 4; g++) {
                    uint32_t khf[4], klf[4];
                    const uint32_t kaddr = sKh + (g*16 + lrq)*ASTRB + kk*32 + lch;
                    ldsm4(khf, kaddr);
                    ldsm4(klf, kaddr + AK_SZ);
                    mma_bf16(s[2*g],   qh[kk], khf[0], khf[2]);
                    mma_bf16(s[2*g+1], qh[kk], khf[1], khf[3]);
                    mma_bf16(s[2*g],   qh[kk], klf[0], klf[2]);
                    mma_bf16(s[2*g+1], qh[kk], klf[1], klf[3]);
                    mma_bf16(s[2*g],   ql[kk], khf[0], khf[2]);
                    mma_bf16(s[2*g+1], ql[kk], khf[1], khf[3]);
                }
            }

            // ---- scale + causal mask ----
            const int r0 = qs + wid*16 + (lane >> 2);
            const int r1 = r0 + 8;
            const float SC = 0.125f;
            if (ks + 63 > qs + wid*16) {
                #pragma unroll
                for (int j = 0; j < 8; j++) {
                    const int c = ks + j*8 + (lane & 3)*2;
                    s[j][0] = (c     <= r0) ? s[j][0]*SC : -1e30f;
                    s[j][1] = (c + 1 <= r0) ? s[j][1]*SC : -1e30f;
                    s[j][2] = (c     <= r1) ? s[j][2]*SC : -1e30f;
                    s[j][3] = (c + 1 <= r1) ? s[j][3]*SC : -1e30f;
                }
            } else {
                #pragma unroll
                for (int j = 0; j < 8; j++) {
                    s[j][0] *= SC; s[j][1] *= SC; s[j][2] *= SC; s[j][3] *= SC;
                }
            }

            // ---- online softmax ----
            float mx0 = -1e30f, mx1 = -1e30f;
            #pragma unroll
            for (int j = 0; j < 8; j++) {
                mx0 = fmaxf(mx0, fmaxf(s[j][0], s[j][1]));
                mx1 = fmaxf(mx1, fmaxf(s[j][2], s[j][3]));
            }
            mx0 = fmaxf(mx0, __shfl_xor_sync(0xffffffffu, mx0, 1));
            mx0 = fmaxf(mx0, __shfl_xor_sync(0xffffffffu, mx0, 2));
            mx1 = fmaxf(mx1, __shfl_xor_sync(0xffffffffu, mx1, 1));
            mx1 = fmaxf(mx1, __shfl_xor_sync(0xffffffffu, mx1, 2));
            const float mn0 = fmaxf(m0r, mx0), mn1 = fmaxf(m1r, mx1);
            const float a0 = __expf(m0r - mn0), a1 = __expf(m1r - mn1);
            m0r = mn0; m1r = mn1;
            float su0 = 0.f, su1 = 0.f;
            #pragma unroll
            for (int j = 0; j < 8; j++) {
                s[j][0] = __expf(s[j][0] - mn0);
                s[j][1] = __expf(s[j][1] - mn0);
                s[j][2] = __expf(s[j][2] - mn1);
                s[j][3] = __expf(s[j][3] - mn1);
                su0 += s[j][0] + s[j][1];
                su1 += s[j][2] + s[j][3];
            }
            su0 += __shfl_xor_sync(0xffffffffu, su0, 1);
            su0 += __shfl_xor_sync(0xffffffffu, su0, 2);
            su1 += __shfl_xor_sync(0xffffffffu, su1, 1);
            su1 += __shfl_xor_sync(0xffffffffu, su1, 2);
            l0r = l0r*a0 + su0;
            l1r = l1r*a1 + su1;
            #pragma unroll
            for (int j = 0; j < 8; j++) {
                o[j][0] *= a0; o[j][1] *= a0; o[j][2] *= a1; o[j][3] *= a1;
            }

            // ---- O += P V ----
            #pragma unroll
            for (int kk = 0; kk < 4; kk++) {
                uint32_t ph[4], pl[4];
                split2(s[2*kk][0],   s[2*kk][1],   ph[0], pl[0]);
                split2(s[2*kk][2],   s[2*kk][3],   ph[1], pl[1]);
                split2(s[2*kk+1][0], s[2*kk+1][1], ph[2], pl[2]);
                split2(s[2*kk+1][2], s[2*kk+1][3], ph[3], pl[3]);
                #pragma unroll
                for (int g = 0; g < 4; g++) {
                    uint32_t vhf[4], vlf[4];
                    const uint32_t vaddr = sVh + (kk*16 + lrq)*ASTRB + g*32 + lch;
                    ldsm4t(vhf, vaddr);
                    ldsm4t(vlf, vaddr + AK_SZ);
                    mma_bf16(o[2*g],   ph, vhf[0], vhf[1]);
                    mma_bf16(o[2*g+1], ph, vhf[2], vhf[3]);
                    mma_bf16(o[2*g],   ph, vlf[0], vlf[1]);
                    mma_bf16(o[2*g+1], ph, vlf[2], vlf[3]);
                    mma_bf16(o[2*g],   pl, vhf[0], vhf[1]);
                    mma_bf16(o[2*g+1], pl, vhf[2], vhf[3]);
                }
            }
        }

        if (t + 1 < nt) CPA_WAIT0();
        __syncthreads();
    }

    // ---- write O split bf16 into [B,S,D] ----
    const float i0 = 1.f / l0r, i1 = 1.f / l1r;
    const int row0 = qs + wid*16 + (lane >> 2);
    const int row1 = row0 + 8;
    const int b = bh >> 4, h = bh & 15;
    #pragma unroll
    for (int j = 0; j < 8; j++) {
        const int c = h*64 + j*8 + (lane & 3)*2;
        const size_t e0 = (size_t)(b*SEQ + row0)*D_MODEL + c;
        const size_t e1 = (size_t)(b*SEQ + row1)*D_MODEL + c;
        uint32_t hi, lo;
        split2(o[j][0]*i0, o[j][1]*i0, hi, lo);
        *(uint32_t*)(Oh_g + e0) = hi;
        *(uint32_t*)(Ol_g + e0) = lo;
        split2(o[j][2]*i1, o[j][3]*i1, hi, lo);
        *(uint32_t*)(Oh_g + e1) = hi;
        *(uint32_t*)(Ol_g + e1) = lo;
    }
}

// =====================================================================
// launch (5 launches; attn is #4 so ncu's capture slot lands on it)
// =====================================================================
extern "C" void kernel_launch(void* const* d_in, const int* in_sizes, int n_in,
                              void* d_out, int out_size)
{
    (void)in_sizes; (void)n_in; (void)out_size;
    const float* x  = (const float*)d_in[0];
    const float* Wq = (const float*)d_in[1];
    const float* bq = (const float*)d_in[2];
    const float* Wk = (const float*)d_in[3];
    const float* bk = (const float*)d_in[4];
    const float* Wv = (const float*)d_in[5];
    const float* bv = (const float*)d_in[6];
    const float* Wo = (const float*)d_in[7];
    const float* bo = (const float*)d_in[8];
    float* out = (float*)d_out;

    __nv_bfloat16 *xh, *xl, *Wh, *Wl, *Qh, *Ql, *Kh, *Kl, *Vh, *Vl, *Oh, *Ol;
    cudaGetSymbolAddress((void**)&xh, g_xh);
    cudaGetSymbolAddress((void**)&xl, g_xl);
    cudaGetSymbolAddress((void**)&Wh, g_Wh);
    cudaGetSymbolAddress((void**)&Wl, g_Wl);
    cudaGetSymbolAddress((void**)&Qh, g_Qh);
    cudaGetSymbolAddress((void**)&Ql, g_Ql);
    cudaGetSymbolAddress((void**)&Kh, g_Kh);
    cudaGetSymbolAddress((void**)&Kl, g_Kl);
    cudaGetSymbolAddress((void**)&Vh, g_Vh);
    cudaGetSymbolAddress((void**)&Vl, g_Vl);
    cudaGetSymbolAddress((void**)&Oh, g_Oh);
    cudaGetSymbolAddress((void**)&Ol, g_Ol);

    cudaFuncSetAttribute(gemm_qkv,
                         cudaFuncAttributeMaxDynamicSharedMemorySize, GEMM_SMEM);
    cudaFuncSetAttribute(gemm_out,
                         cudaFuncAttributeMaxDynamicSharedMemorySize, GEMM_SMEM);
    cudaFuncSetAttribute(attn_mma,
                         cudaFuncAttributeMaxDynamicSharedMemorySize, ATTN_SMEM);

    // 1) split x
    split4_kernel<<<(MROWS*D_MODEL/4 + 255)/256, 256>>>(x, xh, xl, MROWS*D_MODEL/4);
    // 2) split all four weight matrices
    splitW_kernel<<<dim3(DD/4/256, 4), 256>>>(Wq, Wk, Wv, Wo, Wh, Wl);
    // 3) QKV projections + fused RoPE + split
    gemm_qkv<<<dim3(D_MODEL/128, MROWS/128, 3), 256, GEMM_SMEM>>>(
        xh, xl, Wh, Wl, bq, bk, bv, Qh, Ql, Kh, Kl, Vh, Vl);
    // 4) attention  (ncu capture slot)
    attn_mma<<<dim3(SEQ/128, BHTOT), 256, ATTN_SMEM>>>(
        Qh, Ql, Kh, Kl, Vh, Vl, Oh, Ol);
    // 5) output projection
    gemm_out<<<dim3(D_MODEL/128, MROWS/128), 256, GEMM_SMEM>>>(
        Oh, Ol, Wh + 3*DD, Wl + 3*DD, bo, out);
}